// round 6
// baseline (speedup 1.0000x reference)
#include <cuda_runtime.h>
#include <cuda_fp16.h>
#include <cstdint>

#define BB 64
#define CC 64
#define TT 2048
#define HH 128
#define GG 512   // 4H
#define H2 256   // 2H

// Scratch (device globals — no runtime allocation allowed)
__device__ __half g_zin[2][BB][TT][GG];     // 256 MiB input projections (bias folded)
__device__ __half g_y[BB][TT][H2];          // 64 MiB [h_fwd | h_bwd]
__device__ float  g_scores[BB][TT];         // attention logits
__device__ __align__(16) __half g_Wa_h[H2 * H2];    // Wa fp16, row-major [g][k]
__device__ __align__(16) __half g_W1h[1024 * CC];   // [Wih_f; Wih_b] fp16 row-major
__device__ float  g_b1[1024];               // bih+bhh per dir, concatenated

// ---------------- helpers ----------------
__device__ __forceinline__ float fast_ex2(float x) {
    float y; asm("ex2.approx.f32 %0, %1;" : "=f"(y) : "f"(x)); return y;
}
__device__ __forceinline__ float fast_rcp(float x) {
    float y; asm("rcp.approx.f32 %0, %1;" : "=f"(y) : "f"(x)); return y;
}
#define LOG2E 1.4426950408889634f
__device__ __forceinline__ float sigm(float x) {
    return fast_rcp(1.f + fast_ex2(-LOG2E * x));
}
__device__ __forceinline__ float tanha(float x) {
    return 1.f - 2.f * fast_rcp(1.f + fast_ex2(2.f * LOG2E * x));
}
__device__ __forceinline__ float hsum(__half2 a) {
    return __low2float(a) + __high2float(a);
}
__device__ __forceinline__ __half2 u2h(unsigned u) {
    return *reinterpret_cast<__half2*>(&u);
}
__device__ __forceinline__ uint32_t h2u(__half2 h) {
    return *reinterpret_cast<uint32_t*>(&h);
}

// ---------------- cluster / mbarrier plumbing (sm_90 baseline PTX) ----------------
__device__ __forceinline__ uint32_t smem_u32(const void* p) {
    uint32_t a;
    asm("{ .reg .u64 t; cvta.to.shared.u64 t, %1; cvt.u32.u64 %0, t; }" : "=r"(a) : "l"(p));
    return a;
}
__device__ __forceinline__ uint32_t mapa_u32(uint32_t addr, uint32_t rank) {
    uint32_t r;
    asm("mapa.shared::cluster.u32 %0, %1, %2;" : "=r"(r) : "r"(addr), "r"(rank));
    return r;
}
__device__ __forceinline__ void st_cluster_u16(uint32_t addr, __half v) {
    unsigned short u = __half_as_ushort(v);
    asm volatile("st.shared::cluster.u16 [%0], %1;" :: "r"(addr), "h"(u) : "memory");
}
__device__ __forceinline__ void st_cluster_u32(uint32_t addr, uint32_t v) {
    asm volatile("st.shared::cluster.u32 [%0], %1;" :: "r"(addr), "r"(v) : "memory");
}
__device__ __forceinline__ void mbar_init(uint32_t addr, uint32_t cnt) {
    asm volatile("mbarrier.init.shared.b64 [%0], %1;" :: "r"(addr), "r"(cnt) : "memory");
}
__device__ __forceinline__ void mbar_arrive_cluster(uint32_t addr) {
    asm volatile("mbarrier.arrive.release.cluster.shared::cluster.b64 _, [%0];"
                 :: "r"(addr) : "memory");
}
__device__ __forceinline__ void mbar_wait_acq(uint32_t addr, uint32_t parity) {
    asm volatile(
        "{\n\t.reg .pred P;\n\t"
        "W_%=:\n\t"
        "mbarrier.try_wait.parity.acquire.cluster.shared::cta.b64 P, [%0], %1;\n\t"
        "@P bra.uni D_%=;\n\t"
        "bra.uni W_%=;\n\t"
        "D_%=:\n\t}" :: "r"(addr), "r"(parity) : "memory");
}
__device__ __forceinline__ void cluster_sync() {
    asm volatile("barrier.cluster.arrive.aligned;" ::: "memory");
    asm volatile("barrier.cluster.wait.aligned;" ::: "memory");
}

// m16n8k16 row.col f16 -> f32 (base-target PTX, lowers to HMMA on sm_103)
__device__ __forceinline__ void mma16816(float* d, const uint32_t* a,
                                         uint32_t b0, uint32_t b1, const float* c) {
    asm volatile(
        "mma.sync.aligned.m16n8k16.row.col.f32.f16.f16.f32 "
        "{%0,%1,%2,%3}, {%4,%5,%6,%7}, {%8,%9}, {%10,%11,%12,%13};"
        : "=f"(d[0]), "=f"(d[1]), "=f"(d[2]), "=f"(d[3])
        : "r"(a[0]), "r"(a[1]), "r"(a[2]), "r"(a[3]),
          "r"(b0), "r"(b1),
          "f"(c[0]), "f"(c[1]), "f"(c[2]), "f"(c[3]));
}

// ---------------- prep kernels (tiny) ----------------
__global__ void __launch_bounds__(256) p_wa(const float* __restrict__ Wa) {
    int i = blockIdx.x * 256 + threadIdx.x;
    g_Wa_h[i] = __float2half(__ldg(Wa + i));
}
__global__ void __launch_bounds__(256) p_w1(
    const float* __restrict__ Wf, const float* __restrict__ Wb,
    const float* __restrict__ bif, const float* __restrict__ bhf,
    const float* __restrict__ bib, const float* __restrict__ bhb)
{
    int i = blockIdx.x * 256 + threadIdx.x;
    g_W1h[i] = __float2half(i < 32768 ? __ldg(Wf + i) : __ldg(Wb + i - 32768));
    if (i < 512)       g_b1[i] = __ldg(bif + i) + __ldg(bhf + i);
    else if (i < 1024) g_b1[i] = __ldg(bib + i - 512) + __ldg(bhb + i - 512);
}

// ---------------- K1: z = x_tile @ W1^T + bias via mma.sync ----------------
#define K1_WS   0
#define K1_XS   147456
#define K1_BS   164352
#define K1_TOT  168448

__global__ void __launch_bounds__(256) k1_mma(const float* __restrict__ x)
{
    extern __shared__ __align__(16) char smem[];
    const int tid = threadIdx.x;
    const int t0 = blockIdx.x * 128;
    const int b  = blockIdx.y;

    {
        const uint4* src = reinterpret_cast<const uint4*>(g_W1h);
        #pragma unroll
        for (int i = 0; i < 32; i++) {
            int idx = i * 256 + tid;
            int r = idx >> 3, c = idx & 7;
            *reinterpret_cast<uint4*>(smem + K1_WS + r * 144 + c * 16) = __ldg(src + idx);
        }
    }
    #pragma unroll
    for (int i = 0; i < 32; i++) {
        int idx = i * 256 + tid;
        int c = idx >> 7, tl = idx & 127;
        float v = __ldg(x + ((size_t)b * CC + c) * TT + t0 + tl);
        *reinterpret_cast<__half*>(smem + K1_XS + tl * 132 + c * 2) = __float2half(v);
    }
    #pragma unroll
    for (int i = 0; i < 4; i++) {
        int g = i * 256 + tid;
        *reinterpret_cast<float*>(smem + K1_BS + g * 4) = g_b1[g];
    }
    __syncthreads();

    const int w = tid >> 5, lane = tid & 31;
    const int qr = lane >> 2, q4 = lane & 3;
    const int m0 = w * 16;

    uint32_t afr[4][4];
    {
        const char* xb = smem + K1_XS;
        #pragma unroll
        for (int kt = 0; kt < 4; kt++) {
            int kb = q4 * 2 + kt * 16;
            afr[kt][0] = *reinterpret_cast<const uint32_t*>(xb + (m0 + qr) * 132 + kb * 2);
            afr[kt][1] = *reinterpret_cast<const uint32_t*>(xb + (m0 + qr + 8) * 132 + kb * 2);
            afr[kt][2] = *reinterpret_cast<const uint32_t*>(xb + (m0 + qr) * 132 + (kb + 8) * 2);
            afr[kt][3] = *reinterpret_cast<const uint32_t*>(xb + (m0 + qr + 8) * 132 + (kb + 8) * 2);
        }
    }

    const char* wsb = smem + K1_WS;
    const int t_ = t0 + m0 + qr;
    #pragma unroll 4
    for (int j = 0; j < 128; j++) {
        float acc[4] = {0.f, 0.f, 0.f, 0.f};
        int nr = j * 8 + qr;
        #pragma unroll
        for (int kt = 0; kt < 4; kt++) {
            int kb = q4 * 2 + kt * 16;
            uint32_t b0 = *reinterpret_cast<const uint32_t*>(wsb + nr * 144 + kb * 2);
            uint32_t b1 = *reinterpret_cast<const uint32_t*>(wsb + nr * 144 + (kb + 8) * 2);
            mma16816(acc, afr[kt], b0, b1, acc);
        }
        int gcol = j * 8 + q4 * 2;
        float2 bs = *reinterpret_cast<const float2*>(smem + K1_BS + gcol * 4);
        int dir = gcol >> 9, g = gcol & 511;
        __half2 v01 = __floats2half2_rn(acc[0] + bs.x, acc[1] + bs.y);
        __half2 v23 = __floats2half2_rn(acc[2] + bs.x, acc[3] + bs.y);
        *reinterpret_cast<__half2*>(&g_zin[dir][b][t_][g]) = v01;
        *reinterpret_cast<__half2*>(&g_zin[dir][b][t_ + 8][g]) = v23;
    }
}

// ---------------- K2: recurrence, 2-CTA cluster per (b,dir) chain ----------------
// rank 0 (128 thr): rows i,f + c/h state. rank 1 (128 thr): rows g,o.
// Exchange via DSMEM stores + release/acquire mbarriers. 2 CTAs co-resident/SM.
__global__ void __launch_bounds__(128) __cluster_dims__(2, 1, 1)
k2_lstm(const float* __restrict__ Whh_f, const float* __restrict__ Whh_b)
{
    const int rank = blockIdx.x;           // cluster rank along x
    const int b    = blockIdx.y;
    const int dir  = blockIdx.z;
    const int tid  = threadIdx.x;          // 0..127
    const float* Whh = dir ? Whh_b : Whh_f;

    __shared__ __align__(16) __half hs[2][HH];        // h double buffer
    __shared__ __align__(16) uint32_t gbuf[2][HH];    // packed (tanh g, sigm o); rank0 only
    __shared__ __align__(8) unsigned long long mbar;  // rank0: gates-ready; rank1: h-ready

    const int row0 = tid + rank * 256;     // rank0: i-row; rank1: g-row
    const int row1 = row0 + 128;           // rank0: f-row; rank1: o-row

    __half2 w0[64], w1[64];
    {
        const float4* p0 = reinterpret_cast<const float4*>(Whh + row0 * HH);
        const float4* p1 = reinterpret_cast<const float4*>(Whh + row1 * HH);
        #pragma unroll
        for (int k = 0; k < 32; k++) {
            float4 f = __ldg(p0 + k);
            w0[2*k]   = __floats2half2_rn(f.x, f.y);
            w0[2*k+1] = __floats2half2_rn(f.z, f.w);
            float4 g = __ldg(p1 + k);
            w1[2*k]   = __floats2half2_rn(g.x, g.y);
            w1[2*k+1] = __floats2half2_rn(g.z, g.w);
        }
    }
    hs[0][tid] = __float2half(0.f);
    hs[1][tid] = __float2half(0.f);

    const uint32_t mbar_l = smem_u32(&mbar);
    if (tid == 0) mbar_init(mbar_l, 4);    // 4 warps of the peer arrive per step
    __syncthreads();
    cluster_sync();                         // mbar visible cluster-wide before any arrive

    const uint32_t peer      = rank ^ 1;
    const uint32_t peer_mbar = mapa_u32(mbar_l, peer);
    const uint32_t hs_l      = smem_u32(&hs[0][0]);
    const uint32_t peer_hs   = mapa_u32(hs_l, 1);               // rank0 -> rank1's hs
    const uint32_t gbuf_l    = smem_u32(&gbuf[0][0]);
    const uint32_t peer_gbuf = mapa_u32(gbuf_l, 0);             // rank1 -> rank0's gbuf

    const __half* zb = &g_zin[dir][b][0][0];
    int tt = dir ? (TT - 1) : 0;
    const int tstep = dir ? -1 : 1;
    __half* ydst = &g_y[b][0][dir * HH + tid];

    float cst = 0.f;
    uint32_t par = 0;          // parity of this CTA's own mbarrier waits
    const int lane0 = ((tid & 31) == 0);

    // depth-2 z prefetch (2 rows/thread)
    float za0 = __half2float(__ldg(zb + (size_t)tt * GG + row0));
    float za1 = __half2float(__ldg(zb + (size_t)tt * GG + row1));
    float zn0 = __half2float(__ldg(zb + (size_t)(tt + tstep) * GG + row0));
    float zn1 = __half2float(__ldg(zb + (size_t)(tt + tstep) * GG + row1));

    for (int s = 0; s < TT; s++) {
        if (rank == 1 && s > 0) {          // wait for h(s-1) from rank0
            mbar_wait_acq(mbar_l, par);
            par ^= 1;
        }

        float zc0 = za0, zc1 = za1;
        za0 = zn0; za1 = zn1;
        if (s + 2 < TT) {
            const __half* zp = zb + (size_t)(tt + 2 * tstep) * GG;
            zn0 = __half2float(__ldg(zp + row0));
            zn1 = __half2float(__ldg(zp + row1));
        }

        const uint4* hr = reinterpret_cast<const uint4*>(&hs[s & 1][0]);
        __half2 p0 = __float2half2_rn(0.f), p1 = p0, p2 = p0, p3 = p0;
        __half2 q0 = p0, q1 = p0, q2 = p0, q3 = p0;
        #pragma unroll
        for (int q = 0; q < 16; q++) {
            uint4 v = hr[q];
            p0 = __hfma2(w0[4*q+0], u2h(v.x), p0);
            q0 = __hfma2(w1[4*q+0], u2h(v.x), q0);
            p1 = __hfma2(w0[4*q+1], u2h(v.y), p1);
            q1 = __hfma2(w1[4*q+1], u2h(v.y), q1);
            p2 = __hfma2(w0[4*q+2], u2h(v.z), p2);
            q2 = __hfma2(w1[4*q+2], u2h(v.z), q2);
            p3 = __hfma2(w0[4*q+3], u2h(v.w), p3);
            q3 = __hfma2(w1[4*q+3], u2h(v.w), q3);
        }
        __half2 pA = __hadd2(__hadd2(p0, p1), __hadd2(p2, p3));
        __half2 qA = __hadd2(__hadd2(q0, q1), __hadd2(q2, q3));
        float s0 = zc0 + hsum(pA);
        float s1 = zc1 + hsum(qA);

        if (rank == 1) {
            // gates g, o -> activations -> ship to rank0
            float tg = tanha(s0);
            float so = sigm(s1);
            uint32_t pk = h2u(__floats2half2_rn(tg, so));
            st_cluster_u32(peer_gbuf + (uint32_t)(s & 1) * 512u + (uint32_t)tid * 4u, pk);
            __syncwarp();
            if (lane0) mbar_arrive_cluster(peer_mbar);
        } else {
            // gates i, f
            float si = sigm(s0);
            float sf = sigm(s1);
            mbar_wait_acq(mbar_l, par);    // gates(s) from rank1
            par ^= 1;
            __half2 go = u2h(gbuf[s & 1][tid]);
            float tg = __low2float(go), so = __high2float(go);
            cst = sf * cst + si * tg;
            float hv = so * tanha(cst);
            __half hh = __float2half(hv);
            hs[(s + 1) & 1][tid] = hh;
            if (s + 1 < TT) {
                st_cluster_u16(peer_hs + (uint32_t)((s + 1) & 1) * 256u + (uint32_t)tid * 2u, hh);
                __syncwarp();
                if (lane0) mbar_arrive_cluster(peer_mbar);
            }
            ydst[(size_t)tt * H2] = hh;
            __syncthreads();               // order local hs writes before next-step reads
        }
        tt += tstep;
    }
    cluster_sync();                         // keep peer smem alive until exchanges drain
}

// ---------------- K3: attention logits via mma.sync ----------------
#define K3_WA   0
#define K3_YS   135168
#define K3_BW   202752
#define K3_TOT  204800

__global__ void __launch_bounds__(256) k3_mma(
    const float* __restrict__ ba, const float* __restrict__ Wu)
{
    extern __shared__ __align__(16) char smem[];
    const int tid = threadIdx.x;
    const int t0 = blockIdx.x * 128;
    const int b  = blockIdx.y;

    {
        const uint4* src = reinterpret_cast<const uint4*>(g_Wa_h);
        #pragma unroll
        for (int i = 0; i < 32; i++) {
            int idx = i * 256 + tid;
            int r = idx >> 5, c = idx & 31;
            *reinterpret_cast<uint4*>(smem + K3_WA + r * 528 + c * 16) = __ldg(src + idx);
        }
    }
    {
        const uint4* src = reinterpret_cast<const uint4*>(&g_y[b][t0][0]);
        #pragma unroll
        for (int i = 0; i < 16; i++) {
            int idx = i * 256 + tid;
            int r = idx >> 5, c = idx & 31;
            *reinterpret_cast<uint4*>(smem + K3_YS + r * 528 + c * 16) = src[idx];
        }
    }
    *reinterpret_cast<float2*>(smem + K3_BW + tid * 8) =
        make_float2(__ldg(ba + tid), __ldg(Wu + tid));
    __syncthreads();

    const int w = tid >> 5, lane = tid & 31;
    const int qr = lane >> 2, q4 = lane & 3;
    const int m0 = w * 16;

    uint32_t afr[16][4];
    {
        const char* yb = smem + K3_YS;
        #pragma unroll
        for (int kt = 0; kt < 16; kt++) {
            int kb = q4 * 2 + kt * 16;
            afr[kt][0] = *reinterpret_cast<const uint32_t*>(yb + (m0 + qr) * 528 + kb * 2);
            afr[kt][1] = *reinterpret_cast<const uint32_t*>(yb + (m0 + qr + 8) * 528 + kb * 2);
            afr[kt][2] = *reinterpret_cast<const uint32_t*>(yb + (m0 + qr) * 528 + (kb + 8) * 2);
            afr[kt][3] = *reinterpret_cast<const uint32_t*>(yb + (m0 + qr + 8) * 528 + (kb + 8) * 2);
        }
    }

    const char* wab = smem + K3_WA;
    const float2* bw = reinterpret_cast<const float2*>(smem + K3_BW);
    float s0 = 0.f, s1 = 0.f;

    #pragma unroll 2
    for (int j = 0; j < 32; j++) {
        float acc[4] = {0.f, 0.f, 0.f, 0.f};
        int nr = j * 8 + qr;
        #pragma unroll
        for (int kt = 0; kt < 16; kt++) {
            int kb = q4 * 2 + kt * 16;
            uint32_t b0 = *reinterpret_cast<const uint32_t*>(wab + nr * 528 + kb * 2);
            uint32_t b1 = *reinterpret_cast<const uint32_t*>(wab + nr * 528 + (kb + 8) * 2);
            mma16816(acc, afr[kt], b0, b1, acc);
        }
        int n0 = j * 8 + q4 * 2;
        float2 pp0 = bw[n0], pp1 = bw[n0 + 1];
        s0 += tanha(acc[0] + pp0.x) * pp0.y + tanha(acc[1] + pp1.x) * pp1.y;
        s1 += tanha(acc[2] + pp0.x) * pp0.y + tanha(acc[3] + pp1.x) * pp1.y;
    }
    s0 += __shfl_xor_sync(0xffffffffu, s0, 1);
    s0 += __shfl_xor_sync(0xffffffffu, s0, 2);
    s1 += __shfl_xor_sync(0xffffffffu, s1, 1);
    s1 += __shfl_xor_sync(0xffffffffu, s1, 2);
    if (q4 == 0) {
        g_scores[b][t0 + m0 + qr]     = s0;
        g_scores[b][t0 + m0 + qr + 8] = s1;
    }
}

// ---------------- K4: softmax over T + weighted sum ----------------
__global__ void __launch_bounds__(256) k4_soft(float* __restrict__ out)
{
    __shared__ float wb[TT];
    __shared__ float red[256];
    const int b = blockIdx.x, tid = threadIdx.x;

    float m = -1e30f;
    #pragma unroll
    for (int r = 0; r < 8; r++) m = fmaxf(m, g_scores[b][r * 256 + tid]);
    red[tid] = m; __syncthreads();
    for (int off = 128; off > 0; off >>= 1) {
        if (tid < off) red[tid] = fmaxf(red[tid], red[tid + off]);
        __syncthreads();
    }
    const float mx = red[0];
    __syncthreads();

    float ls = 0.f;
    #pragma unroll
    for (int r = 0; r < 8; r++) {
        int t = r * 256 + tid;
        float e = fast_ex2((g_scores[b][t] - mx) * LOG2E);
        wb[t] = e; ls += e;
    }
    red[tid] = ls; __syncthreads();
    for (int off = 128; off > 0; off >>= 1) {
        if (tid < off) red[tid] += red[tid + off];
        __syncthreads();
    }
    const float rz = __frcp_rn(red[0]);

    float acc = 0.f;
    const __half* yp = &g_y[b][0][tid];
    for (int t = 0; t < TT; t += 8) {
        #pragma unroll
        for (int u = 0; u < 8; u++)
            acc += wb[t + u] * __half2float(__ldg(yp + (size_t)(t + u) * H2));
    }
    out[b * H2 + tid] = acc * rz;
}

// ---------------- launch ----------------
extern "C" void kernel_launch(void* const* d_in, const int* in_sizes, int n_in,
                              void* d_out, int out_size)
{
    const float* x     = (const float*)d_in[0];
    const float* Wih_f = (const float*)d_in[1];
    const float* Whh_f = (const float*)d_in[2];
    const float* bih_f = (const float*)d_in[3];
    const float* bhh_f = (const float*)d_in[4];
    const float* Wih_b = (const float*)d_in[5];
    const float* Whh_b = (const float*)d_in[6];
    const float* bih_b = (const float*)d_in[7];
    const float* bhh_b = (const float*)d_in[8];
    const float* Wa    = (const float*)d_in[9];
    const float* ba    = (const float*)d_in[10];
    const float* Wu    = (const float*)d_in[11];
    float* out = (float*)d_out;

    cudaFuncSetAttribute(k1_mma, cudaFuncAttributeMaxDynamicSharedMemorySize, K1_TOT);
    cudaFuncSetAttribute(k3_mma, cudaFuncAttributeMaxDynamicSharedMemorySize, K3_TOT);

    p_wa<<<256, 256>>>(Wa);
    p_w1<<<256, 256>>>(Wih_f, Wih_b, bih_f, bhh_f, bih_b, bhh_b);
    k1_mma<<<dim3(TT / 128, BB), 256, K1_TOT>>>(x);
    k2_lstm<<<dim3(2, BB, 2), 128>>>(Whh_f, Whh_b);   // 2-CTA clusters along x
    k3_mma<<<dim3(TT / 128, BB), 256, K3_TOT>>>(ba, Wu);
    k4_soft<<<BB, 256>>>(out);
}

// round 7
// speedup vs baseline: 1.0464x; 1.0464x over previous
#include <cuda_runtime.h>
#include <cuda_fp16.h>
#include <cstdint>

#define BB 64
#define CC 64
#define TT 2048
#define HH 128
#define GG 512   // 4H
#define H2 256   // 2H

// Scratch (device globals — no runtime allocation allowed)
__device__ __half g_zin[2][BB][TT][GG];     // 256 MiB input projections (bias folded)
__device__ __half g_y[BB][TT][H2];          // 64 MiB [h_fwd | h_bwd]
__device__ float  g_scores[BB][TT];         // attention logits
__device__ __align__(16) __half g_Wa_h[H2 * H2];    // Wa fp16, row-major [g][k]
__device__ __align__(16) __half g_W1h[1024 * CC];   // [Wih_f; Wih_b] fp16 row-major
__device__ float  g_b1[1024];               // bih+bhh per dir, concatenated

// ---------------- helpers ----------------
__device__ __forceinline__ float fast_ex2(float x) {
    float y; asm("ex2.approx.f32 %0, %1;" : "=f"(y) : "f"(x)); return y;
}
__device__ __forceinline__ float fast_rcp(float x) {
    float y; asm("rcp.approx.f32 %0, %1;" : "=f"(y) : "f"(x)); return y;
}
#define LOG2E 1.4426950408889634f
__device__ __forceinline__ float sigm(float x) {      // accurate (ex2+rcp), for gates
    return fast_rcp(1.f + fast_ex2(-LOG2E * x));
}
__device__ __forceinline__ float tanha(float x) {     // accurate, for gate g
    return 1.f - 2.f * fast_rcp(1.f + fast_ex2(2.f * LOG2E * x));
}
__device__ __forceinline__ float ftanh(float x) {     // MUFU.TANH, for tanh(c) & attention
    float y; asm("tanh.approx.f32 %0, %1;" : "=f"(y) : "f"(x)); return y;
}
__device__ __forceinline__ float hsum(__half2 a) {
    return __low2float(a) + __high2float(a);
}
__device__ __forceinline__ float hsum4(__half2 a, __half2 b, __half2 c, __half2 d) {
    __half2 s = __hadd2(__hadd2(a, b), __hadd2(c, d));
    return __low2float(s) + __high2float(s);
}
__device__ __forceinline__ __half2 u2h(unsigned u) {
    return *reinterpret_cast<__half2*>(&u);
}

// m16n8k16 row.col f16 -> f32 (base-target PTX, lowers to HMMA on sm_103)
__device__ __forceinline__ void mma16816(float* d, const uint32_t* a,
                                         uint32_t b0, uint32_t b1, const float* c) {
    asm volatile(
        "mma.sync.aligned.m16n8k16.row.col.f32.f16.f16.f32 "
        "{%0,%1,%2,%3}, {%4,%5,%6,%7}, {%8,%9}, {%10,%11,%12,%13};"
        : "=f"(d[0]), "=f"(d[1]), "=f"(d[2]), "=f"(d[3])
        : "r"(a[0]), "r"(a[1]), "r"(a[2]), "r"(a[3]),
          "r"(b0), "r"(b1),
          "f"(c[0]), "f"(c[1]), "f"(c[2]), "f"(c[3]));
}

// ---------------- prep kernels (tiny) ----------------
__global__ void __launch_bounds__(256) p_wa(const float* __restrict__ Wa) {
    int i = blockIdx.x * 256 + threadIdx.x;
    g_Wa_h[i] = __float2half(__ldg(Wa + i));
}
__global__ void __launch_bounds__(256) p_w1(
    const float* __restrict__ Wf, const float* __restrict__ Wb,
    const float* __restrict__ bif, const float* __restrict__ bhf,
    const float* __restrict__ bib, const float* __restrict__ bhb)
{
    int i = blockIdx.x * 256 + threadIdx.x;
    g_W1h[i] = __float2half(i < 32768 ? __ldg(Wf + i) : __ldg(Wb + i - 32768));
    if (i < 512)       g_b1[i] = __ldg(bif + i) + __ldg(bhf + i);
    else if (i < 1024) g_b1[i] = __ldg(bib + i - 512) + __ldg(bhb + i - 512);
}

// ---------------- K1: z = x_tile @ W1^T + bias via mma.sync ----------------
#define K1_WS   0
#define K1_XS   147456
#define K1_BS   164352
#define K1_TOT  168448

__global__ void __launch_bounds__(256) k1_mma(const float* __restrict__ x)
{
    extern __shared__ __align__(16) char smem[];
    const int tid = threadIdx.x;
    const int t0 = blockIdx.x * 128;
    const int b  = blockIdx.y;

    {
        const uint4* src = reinterpret_cast<const uint4*>(g_W1h);
        #pragma unroll
        for (int i = 0; i < 32; i++) {
            int idx = i * 256 + tid;
            int r = idx >> 3, c = idx & 7;
            *reinterpret_cast<uint4*>(smem + K1_WS + r * 144 + c * 16) = __ldg(src + idx);
        }
    }
    #pragma unroll
    for (int i = 0; i < 32; i++) {
        int idx = i * 256 + tid;
        int c = idx >> 7, tl = idx & 127;
        float v = __ldg(x + ((size_t)b * CC + c) * TT + t0 + tl);
        *reinterpret_cast<__half*>(smem + K1_XS + tl * 132 + c * 2) = __float2half(v);
    }
    #pragma unroll
    for (int i = 0; i < 4; i++) {
        int g = i * 256 + tid;
        *reinterpret_cast<float*>(smem + K1_BS + g * 4) = g_b1[g];
    }
    __syncthreads();

    const int w = tid >> 5, lane = tid & 31;
    const int qr = lane >> 2, q4 = lane & 3;
    const int m0 = w * 16;

    uint32_t afr[4][4];
    {
        const char* xb = smem + K1_XS;
        #pragma unroll
        for (int kt = 0; kt < 4; kt++) {
            int kb = q4 * 2 + kt * 16;
            afr[kt][0] = *reinterpret_cast<const uint32_t*>(xb + (m0 + qr) * 132 + kb * 2);
            afr[kt][1] = *reinterpret_cast<const uint32_t*>(xb + (m0 + qr + 8) * 132 + kb * 2);
            afr[kt][2] = *reinterpret_cast<const uint32_t*>(xb + (m0 + qr) * 132 + (kb + 8) * 2);
            afr[kt][3] = *reinterpret_cast<const uint32_t*>(xb + (m0 + qr + 8) * 132 + (kb + 8) * 2);
        }
    }

    const char* wsb = smem + K1_WS;
    const int t_ = t0 + m0 + qr;
    #pragma unroll 4
    for (int j = 0; j < 128; j++) {
        float acc[4] = {0.f, 0.f, 0.f, 0.f};
        int nr = j * 8 + qr;
        #pragma unroll
        for (int kt = 0; kt < 4; kt++) {
            int kb = q4 * 2 + kt * 16;
            uint32_t b0 = *reinterpret_cast<const uint32_t*>(wsb + nr * 144 + kb * 2);
            uint32_t b1 = *reinterpret_cast<const uint32_t*>(wsb + nr * 144 + (kb + 8) * 2);
            mma16816(acc, afr[kt], b0, b1, acc);
        }
        int gcol = j * 8 + q4 * 2;
        float2 bs = *reinterpret_cast<const float2*>(smem + K1_BS + gcol * 4);
        int dir = gcol >> 9, g = gcol & 511;
        __half2 v01 = __floats2half2_rn(acc[0] + bs.x, acc[1] + bs.y);
        __half2 v23 = __floats2half2_rn(acc[2] + bs.x, acc[3] + bs.y);
        *reinterpret_cast<__half2*>(&g_zin[dir][b][t_][g]) = v01;
        *reinterpret_cast<__half2*>(&g_zin[dir][b][t_ + 8][g]) = v23;
    }
}

// ---------------- K2: recurrence — TWO batch chains per CTA (shared weights) -------
// warp w lane L: element e = w*16 + (L&15). L<16 owns rows (i,f)+state; L>=16 owns
// (g,o) and ships activations via shfl. Two batches (A,B) advance per step; B's FMA
// issue hides A's tail latency. One __syncthreads per step; h double-buffered.
__global__ void __launch_bounds__(256) k2_lstm(
    const float* __restrict__ Whh_f, const float* __restrict__ Whh_b)
{
    const int dir = blockIdx.y, tid = threadIdx.x;
    const int bA = blockIdx.x * 2, bB = bA + 1;
    const float* Whh = dir ? Whh_b : Whh_f;

    __shared__ __align__(16) __half hsA[2][HH];
    __shared__ __align__(16) __half hsB[2][HH];

    const int w = tid >> 5, lane = tid & 31;
    const int e  = w * 16 + (lane & 15);
    const int hi = lane >> 4;                 // 0: (i,f)+state  1: (g,o)
    const int row0 = e + hi * 256;            // i-row or g-row
    const int row1 = row0 + 128;              // f-row or o-row

    __half2 w0[64], w1[64];
    {
        const float4* p0 = reinterpret_cast<const float4*>(Whh + row0 * HH);
        const float4* p1 = reinterpret_cast<const float4*>(Whh + row1 * HH);
        #pragma unroll
        for (int k = 0; k < 32; k++) {
            float4 f = __ldg(p0 + k);
            w0[2*k]   = __floats2half2_rn(f.x, f.y);
            w0[2*k+1] = __floats2half2_rn(f.z, f.w);
            float4 g = __ldg(p1 + k);
            w1[2*k]   = __floats2half2_rn(g.x, g.y);
            w1[2*k+1] = __floats2half2_rn(g.z, g.w);
        }
    }
    if (tid < HH) {
        hsA[0][tid] = __float2half(0.f); hsA[1][tid] = __float2half(0.f);
        hsB[0][tid] = __float2half(0.f); hsB[1][tid] = __float2half(0.f);
    }
    float cA = 0.f, cB = 0.f;
    __syncthreads();

    const __half* zA = &g_zin[dir][bA][0][0];
    const __half* zB = &g_zin[dir][bB][0][0];
    int tt = dir ? (TT - 1) : 0;
    const int tstep = dir ? -1 : 1;
    __half* ydA = &g_y[bA][0][dir * HH + e];
    __half* ydB = &g_y[bB][0][dir * HH + e];

    // depth-2 z prefetch: 4 rows (A0,A1,B0,B1)
    float zcA0 = __half2float(__ldg(zA + (size_t)tt * GG + row0));
    float zcA1 = __half2float(__ldg(zA + (size_t)tt * GG + row1));
    float zcB0 = __half2float(__ldg(zB + (size_t)tt * GG + row0));
    float zcB1 = __half2float(__ldg(zB + (size_t)tt * GG + row1));
    float znA0 = __half2float(__ldg(zA + (size_t)(tt + tstep) * GG + row0));
    float znA1 = __half2float(__ldg(zA + (size_t)(tt + tstep) * GG + row1));
    float znB0 = __half2float(__ldg(zB + (size_t)(tt + tstep) * GG + row0));
    float znB1 = __half2float(__ldg(zB + (size_t)(tt + tstep) * GG + row1));

    for (int s = 0; s < TT; s++) {
        float a0 = zcA0, a1 = zcA1, b0 = zcB0, b1 = zcB1;
        zcA0 = znA0; zcA1 = znA1; zcB0 = znB0; zcB1 = znB1;
        if (s + 2 < TT) {
            size_t zo = (size_t)(tt + 2 * tstep) * GG;
            znA0 = __half2float(__ldg(zA + zo + row0));
            znA1 = __half2float(__ldg(zA + zo + row1));
            znB0 = __half2float(__ldg(zB + zo + row0));
            znB1 = __half2float(__ldg(zB + zo + row1));
        }

        const uint4* hA = reinterpret_cast<const uint4*>(&hsA[s & 1][0]);
        const uint4* hB = reinterpret_cast<const uint4*>(&hsB[s & 1][0]);
        const __half2 zz = __float2half2_rn(0.f);
        __half2 pA0 = zz, pA1 = zz, pA2 = zz, pA3 = zz;
        __half2 qA0 = zz, qA1 = zz, qA2 = zz, qA3 = zz;
        __half2 pB0 = zz, pB1 = zz, pB2 = zz, pB3 = zz;
        __half2 qB0 = zz, qB1 = zz, qB2 = zz, qB3 = zz;
        #pragma unroll
        for (int q = 0; q < 16; q++) {
            uint4 vA = hA[q];
            uint4 vB = hB[q];
            pA0 = __hfma2(w0[4*q+0], u2h(vA.x), pA0);
            qA0 = __hfma2(w1[4*q+0], u2h(vA.x), qA0);
            pB0 = __hfma2(w0[4*q+0], u2h(vB.x), pB0);
            qB0 = __hfma2(w1[4*q+0], u2h(vB.x), qB0);
            pA1 = __hfma2(w0[4*q+1], u2h(vA.y), pA1);
            qA1 = __hfma2(w1[4*q+1], u2h(vA.y), qA1);
            pB1 = __hfma2(w0[4*q+1], u2h(vB.y), pB1);
            qB1 = __hfma2(w1[4*q+1], u2h(vB.y), qB1);
            pA2 = __hfma2(w0[4*q+2], u2h(vA.z), pA2);
            qA2 = __hfma2(w1[4*q+2], u2h(vA.z), qA2);
            pB2 = __hfma2(w0[4*q+2], u2h(vB.z), pB2);
            qB2 = __hfma2(w1[4*q+2], u2h(vB.z), qB2);
            pA3 = __hfma2(w0[4*q+3], u2h(vA.w), pA3);
            qA3 = __hfma2(w1[4*q+3], u2h(vA.w), qA3);
            pB3 = __hfma2(w0[4*q+3], u2h(vB.w), pB3);
            qB3 = __hfma2(w1[4*q+3], u2h(vB.w), qB3);
        }
        float sA0 = a0 + hsum4(pA0, pA1, pA2, pA3);
        float sA1 = a1 + hsum4(qA0, qA1, qA2, qA3);
        float sB0 = b0 + hsum4(pB0, pB1, pB2, pB3);
        float sB1 = b1 + hsum4(qB0, qB1, qB2, qB3);

        // lanes<16: n0=sigm(i), n1=sigm(f); lanes>=16: n0=tanh(g), n1=sigm(o)
        float nA0 = hi ? tanha(sA0) : sigm(sA0);
        float nB0 = hi ? tanha(sB0) : sigm(sB0);
        float nA1 = sigm(sA1);
        float nB1 = sigm(sB1);
        float rA0 = __shfl_down_sync(0xffffffffu, nA0, 16);
        float rA1 = __shfl_down_sync(0xffffffffu, nA1, 16);
        float rB0 = __shfl_down_sync(0xffffffffu, nB0, 16);
        float rB1 = __shfl_down_sync(0xffffffffu, nB1, 16);

        if (hi == 0) {
            cA = nA1 * cA + nA0 * rA0;
            cB = nB1 * cB + nB0 * rB0;
            float hvA = rA1 * ftanh(cA);
            float hvB = rB1 * ftanh(cB);
            __half hhA = __float2half(hvA);
            __half hhB = __float2half(hvB);
            hsA[(s + 1) & 1][e] = hhA;
            hsB[(s + 1) & 1][e] = hhB;
            ydA[(size_t)tt * H2] = hhA;
            ydB[(size_t)tt * H2] = hhB;
        }
        __syncthreads();
        tt += tstep;
    }
}

// ---------------- K3: attention logits via mma.sync ----------------
#define K3_WA   0
#define K3_YS   135168
#define K3_BW   202752
#define K3_TOT  204800

__global__ void __launch_bounds__(256) k3_mma(
    const float* __restrict__ ba, const float* __restrict__ Wu)
{
    extern __shared__ __align__(16) char smem[];
    const int tid = threadIdx.x;
    const int t0 = blockIdx.x * 128;
    const int b  = blockIdx.y;

    {
        const uint4* src = reinterpret_cast<const uint4*>(g_Wa_h);
        #pragma unroll
        for (int i = 0; i < 32; i++) {
            int idx = i * 256 + tid;
            int r = idx >> 5, c = idx & 31;
            *reinterpret_cast<uint4*>(smem + K3_WA + r * 528 + c * 16) = __ldg(src + idx);
        }
    }
    {
        const uint4* src = reinterpret_cast<const uint4*>(&g_y[b][t0][0]);
        #pragma unroll
        for (int i = 0; i < 16; i++) {
            int idx = i * 256 + tid;
            int r = idx >> 5, c = idx & 31;
            *reinterpret_cast<uint4*>(smem + K3_YS + r * 528 + c * 16) = src[idx];
        }
    }
    *reinterpret_cast<float2*>(smem + K3_BW + tid * 8) =
        make_float2(__ldg(ba + tid), __ldg(Wu + tid));
    __syncthreads();

    const int w = tid >> 5, lane = tid & 31;
    const int qr = lane >> 2, q4 = lane & 3;
    const int m0 = w * 16;

    uint32_t afr[16][4];
    {
        const char* yb = smem + K3_YS;
        #pragma unroll
        for (int kt = 0; kt < 16; kt++) {
            int kb = q4 * 2 + kt * 16;
            afr[kt][0] = *reinterpret_cast<const uint32_t*>(yb + (m0 + qr) * 528 + kb * 2);
            afr[kt][1] = *reinterpret_cast<const uint32_t*>(yb + (m0 + qr + 8) * 528 + kb * 2);
            afr[kt][2] = *reinterpret_cast<const uint32_t*>(yb + (m0 + qr) * 528 + (kb + 8) * 2);
            afr[kt][3] = *reinterpret_cast<const uint32_t*>(yb + (m0 + qr + 8) * 528 + (kb + 8) * 2);
        }
    }

    const char* wab = smem + K3_WA;
    const float2* bw = reinterpret_cast<const float2*>(smem + K3_BW);
    float s0 = 0.f, s1 = 0.f;

    #pragma unroll 2
    for (int j = 0; j < 32; j++) {
        float acc[4] = {0.f, 0.f, 0.f, 0.f};
        int nr = j * 8 + qr;
        #pragma unroll
        for (int kt = 0; kt < 16; kt++) {
            int kb = q4 * 2 + kt * 16;
            uint32_t b0 = *reinterpret_cast<const uint32_t*>(wab + nr * 528 + kb * 2);
            uint32_t b1 = *reinterpret_cast<const uint32_t*>(wab + nr * 528 + (kb + 8) * 2);
            mma16816(acc, afr[kt], b0, b1, acc);
        }
        int n0 = j * 8 + q4 * 2;
        float2 pp0 = bw[n0], pp1 = bw[n0 + 1];
        s0 += ftanh(acc[0] + pp0.x) * pp0.y + ftanh(acc[1] + pp1.x) * pp1.y;
        s1 += ftanh(acc[2] + pp0.x) * pp0.y + ftanh(acc[3] + pp1.x) * pp1.y;
    }
    s0 += __shfl_xor_sync(0xffffffffu, s0, 1);
    s0 += __shfl_xor_sync(0xffffffffu, s0, 2);
    s1 += __shfl_xor_sync(0xffffffffu, s1, 1);
    s1 += __shfl_xor_sync(0xffffffffu, s1, 2);
    if (q4 == 0) {
        g_scores[b][t0 + m0 + qr]     = s0;
        g_scores[b][t0 + m0 + qr + 8] = s1;
    }
}

// ---------------- K4: softmax over T + weighted sum ----------------
__global__ void __launch_bounds__(256) k4_soft(float* __restrict__ out)
{
    __shared__ float wb[TT];
    __shared__ float red[256];
    const int b = blockIdx.x, tid = threadIdx.x;

    float m = -1e30f;
    #pragma unroll
    for (int r = 0; r < 8; r++) m = fmaxf(m, g_scores[b][r * 256 + tid]);
    red[tid] = m; __syncthreads();
    for (int off = 128; off > 0; off >>= 1) {
        if (tid < off) red[tid] = fmaxf(red[tid], red[tid + off]);
        __syncthreads();
    }
    const float mx = red[0];
    __syncthreads();

    float ls = 0.f;
    #pragma unroll
    for (int r = 0; r < 8; r++) {
        int t = r * 256 + tid;
        float e = fast_ex2((g_scores[b][t] - mx) * LOG2E);
        wb[t] = e; ls += e;
    }
    red[tid] = ls; __syncthreads();
    for (int off = 128; off > 0; off >>= 1) {
        if (tid < off) red[tid] += red[tid + off];
        __syncthreads();
    }
    const float rz = __frcp_rn(red[0]);

    float acc = 0.f;
    const __half* yp = &g_y[b][0][tid];
    for (int t = 0; t < TT; t += 8) {
        #pragma unroll
        for (int u = 0; u < 8; u++)
            acc += wb[t + u] * __half2float(__ldg(yp + (size_t)(t + u) * H2));
    }
    out[b * H2 + tid] = acc * rz;
}

// ---------------- launch ----------------
extern "C" void kernel_launch(void* const* d_in, const int* in_sizes, int n_in,
                              void* d_out, int out_size)
{
    const float* x     = (const float*)d_in[0];
    const float* Wih_f = (const float*)d_in[1];
    const float* Whh_f = (const float*)d_in[2];
    const float* bih_f = (const float*)d_in[3];
    const float* bhh_f = (const float*)d_in[4];
    const float* Wih_b = (const float*)d_in[5];
    const float* Whh_b = (const float*)d_in[6];
    const float* bih_b = (const float*)d_in[7];
    const float* bhh_b = (const float*)d_in[8];
    const float* Wa    = (const float*)d_in[9];
    const float* ba    = (const float*)d_in[10];
    const float* Wu    = (const float*)d_in[11];
    float* out = (float*)d_out;

    cudaFuncSetAttribute(k1_mma, cudaFuncAttributeMaxDynamicSharedMemorySize, K1_TOT);
    cudaFuncSetAttribute(k3_mma, cudaFuncAttributeMaxDynamicSharedMemorySize, K3_TOT);

    p_wa<<<256, 256>>>(Wa);
    p_w1<<<256, 256>>>(Wih_f, Wih_b, bih_f, bhh_f, bih_b, bhh_b);
    k1_mma<<<dim3(TT / 128, BB), 256, K1_TOT>>>(x);
    k2_lstm<<<dim3(BB / 2, 2), 256>>>(Whh_f, Whh_b);   // 2 batch chains per CTA
    k3_mma<<<dim3(TT / 128, BB), 256, K3_TOT>>>(ba, Wu);
    k4_soft<<<BB, 256>>>(out);
}

// round 8
// speedup vs baseline: 1.2823x; 1.2254x over previous
#include <cuda_runtime.h>
#include <cuda_fp16.h>
#include <cstdint>

#define BB 64
#define CC 64
#define TT 2048
#define HH 128
#define GG 512   // 4H
#define H2 256   // 2H

// Scratch (device globals — no runtime allocation allowed)
__device__ __half g_zin[2][BB][TT][GG];     // 256 MiB input projections (bias folded)
__device__ __half g_y[BB][TT][H2];          // 64 MiB [h_fwd | h_bwd]
__device__ float  g_scores[BB][TT];         // attention logits
__device__ __align__(16) __half g_Wa_h[H2 * H2];    // Wa fp16, row-major [g][k]
__device__ __align__(16) __half g_W1h[1024 * CC];   // [Wih_f; Wih_b] fp16 row-major
__device__ float  g_b1[1024];               // bih+bhh per dir, concatenated

// ---------------- helpers ----------------
__device__ __forceinline__ float fast_ex2(float x) {
    float y; asm("ex2.approx.f32 %0, %1;" : "=f"(y) : "f"(x)); return y;
}
__device__ __forceinline__ float fast_rcp(float x) {
    float y; asm("rcp.approx.f32 %0, %1;" : "=f"(y) : "f"(x)); return y;
}
#define LOG2E 1.4426950408889634f
__device__ __forceinline__ float sigm(float x) {      // accurate (ex2+rcp)
    return fast_rcp(1.f + fast_ex2(-LOG2E * x));
}
__device__ __forceinline__ float tanha(float x) {     // accurate, for gate g
    return 1.f - 2.f * fast_rcp(1.f + fast_ex2(2.f * LOG2E * x));
}
__device__ __forceinline__ float ftanh(float x) {     // MUFU.TANH (rel_err-neutral, R7)
    float y; asm("tanh.approx.f32 %0, %1;" : "=f"(y) : "f"(x)); return y;
}
__device__ __forceinline__ float hsum4(__half2 a, __half2 b, __half2 c, __half2 d) {
    __half2 s = __hadd2(__hadd2(a, b), __hadd2(c, d));
    return __low2float(s) + __high2float(s);
}
__device__ __forceinline__ __half2 u2h(unsigned u) {
    return *reinterpret_cast<__half2*>(&u);
}
__device__ __forceinline__ uint32_t h2u(__half2 h) {
    return *reinterpret_cast<uint32_t*>(&h);
}

// m16n8k16 row.col f16 -> f32 (base-target PTX, lowers to HMMA on sm_103)
__device__ __forceinline__ void mma16816(float* d, const uint32_t* a,
                                         uint32_t b0, uint32_t b1, const float* c) {
    asm volatile(
        "mma.sync.aligned.m16n8k16.row.col.f32.f16.f16.f32 "
        "{%0,%1,%2,%3}, {%4,%5,%6,%7}, {%8,%9}, {%10,%11,%12,%13};"
        : "=f"(d[0]), "=f"(d[1]), "=f"(d[2]), "=f"(d[3])
        : "r"(a[0]), "r"(a[1]), "r"(a[2]), "r"(a[3]),
          "r"(b0), "r"(b1),
          "f"(c[0]), "f"(c[1]), "f"(c[2]), "f"(c[3]));
}

// ---------------- prep kernels (tiny) ----------------
__global__ void __launch_bounds__(256) p_wa(const float* __restrict__ Wa) {
    int i = blockIdx.x * 256 + threadIdx.x;
    g_Wa_h[i] = __float2half(__ldg(Wa + i));
}
__global__ void __launch_bounds__(256) p_w1(
    const float* __restrict__ Wf, const float* __restrict__ Wb,
    const float* __restrict__ bif, const float* __restrict__ bhf,
    const float* __restrict__ bib, const float* __restrict__ bhb)
{
    int i = blockIdx.x * 256 + threadIdx.x;
    g_W1h[i] = __float2half(i < 32768 ? __ldg(Wf + i) : __ldg(Wb + i - 32768));
    if (i < 512)       g_b1[i] = __ldg(bif + i) + __ldg(bhf + i);
    else if (i < 1024) g_b1[i] = __ldg(bib + i - 512) + __ldg(bhb + i - 512);
}

// ---------------- K1: z = x_tile @ W1^T + bias via mma.sync ----------------
#define K1_WS   0
#define K1_XS   147456
#define K1_BS   164352
#define K1_TOT  168448

__global__ void __launch_bounds__(256) k1_mma(const float* __restrict__ x)
{
    extern __shared__ __align__(16) char smem[];
    const int tid = threadIdx.x;
    const int t0 = blockIdx.x * 128;
    const int b  = blockIdx.y;

    {
        const uint4* src = reinterpret_cast<const uint4*>(g_W1h);
        #pragma unroll
        for (int i = 0; i < 32; i++) {
            int idx = i * 256 + tid;
            int r = idx >> 3, c = idx & 7;
            *reinterpret_cast<uint4*>(smem + K1_WS + r * 144 + c * 16) = __ldg(src + idx);
        }
    }
    #pragma unroll
    for (int i = 0; i < 32; i++) {
        int idx = i * 256 + tid;
        int c = idx >> 7, tl = idx & 127;
        float v = __ldg(x + ((size_t)b * CC + c) * TT + t0 + tl);
        *reinterpret_cast<__half*>(smem + K1_XS + tl * 132 + c * 2) = __float2half(v);
    }
    #pragma unroll
    for (int i = 0; i < 4; i++) {
        int g = i * 256 + tid;
        *reinterpret_cast<float*>(smem + K1_BS + g * 4) = g_b1[g];
    }
    __syncthreads();

    const int w = tid >> 5, lane = tid & 31;
    const int qr = lane >> 2, q4 = lane & 3;
    const int m0 = w * 16;

    uint32_t afr[4][4];
    {
        const char* xb = smem + K1_XS;
        #pragma unroll
        for (int kt = 0; kt < 4; kt++) {
            int kb = q4 * 2 + kt * 16;
            afr[kt][0] = *reinterpret_cast<const uint32_t*>(xb + (m0 + qr) * 132 + kb * 2);
            afr[kt][1] = *reinterpret_cast<const uint32_t*>(xb + (m0 + qr + 8) * 132 + kb * 2);
            afr[kt][2] = *reinterpret_cast<const uint32_t*>(xb + (m0 + qr) * 132 + (kb + 8) * 2);
            afr[kt][3] = *reinterpret_cast<const uint32_t*>(xb + (m0 + qr + 8) * 132 + (kb + 8) * 2);
        }
    }

    const char* wsb = smem + K1_WS;
    const int t_ = t0 + m0 + qr;
    #pragma unroll 4
    for (int j = 0; j < 128; j++) {
        float acc[4] = {0.f, 0.f, 0.f, 0.f};
        int nr = j * 8 + qr;
        #pragma unroll
        for (int kt = 0; kt < 4; kt++) {
            int kb = q4 * 2 + kt * 16;
            uint32_t b0 = *reinterpret_cast<const uint32_t*>(wsb + nr * 144 + kb * 2);
            uint32_t b1 = *reinterpret_cast<const uint32_t*>(wsb + nr * 144 + (kb + 8) * 2);
            mma16816(acc, afr[kt], b0, b1, acc);
        }
        int gcol = j * 8 + q4 * 2;
        float2 bs = *reinterpret_cast<const float2*>(smem + K1_BS + gcol * 4);
        int dir = gcol >> 9, g = gcol & 511;
        __half2 v01 = __floats2half2_rn(acc[0] + bs.x, acc[1] + bs.y);
        __half2 v23 = __floats2half2_rn(acc[2] + bs.x, acc[3] + bs.y);
        *reinterpret_cast<__half2*>(&g_zin[dir][b][t_][g]) = v01;
        *reinterpret_cast<__half2*>(&g_zin[dir][b][t_ + 8][g]) = v23;
    }
}

// ---------------- K2: recurrence — 512 thr, 1 row/thread, shfl exchange ----------
// warp w (16), lane L: element e = w*8 + (L&7), quarter q = L>>3 owns gate q of e
// (order i,f,g,o). Acts computed in parallel by all lanes; two packed shfl hops
// deliver (g) then (f,o) to the q=0 lanes, which own c/h. One barrier per step,
// double-buffered h (no WAR race). 64 weight regs/thread -> ~105 total.
__global__ void __launch_bounds__(512) k2_lstm(
    const float* __restrict__ Whh_f, const float* __restrict__ Whh_b)
{
    const int b = blockIdx.x, dir = blockIdx.y, tid = threadIdx.x;
    const float* Whh = dir ? Whh_b : Whh_f;

    __shared__ __align__(16) __half hs[2][HH];

    const int L = tid & 31, w = tid >> 5;
    const int e = w * 8 + (L & 7);
    const int q = L >> 3;                   // 0:i 1:f 2:g 3:o
    const int row = e + q * 128;

    __half2 wv[64];
    {
        const float4* p = reinterpret_cast<const float4*>(Whh + row * HH);
        #pragma unroll
        for (int k = 0; k < 32; k++) {
            float4 f = __ldg(p + k);
            wv[2*k]   = __floats2half2_rn(f.x, f.y);
            wv[2*k+1] = __floats2half2_rn(f.z, f.w);
        }
    }
    if (tid < HH) {
        hs[0][tid] = __float2half(0.f);
        hs[1][tid] = __float2half(0.f);
    }
    float cst = 0.f;
    __syncthreads();

    const __half* zb = &g_zin[dir][b][0][0];
    int tt = dir ? (TT - 1) : 0;
    const int tstep = dir ? -1 : 1;
    __half* ydst = &g_y[b][0][dir * HH + e];

    // depth-2 z prefetch (1 row/thread)
    float zc = __half2float(__ldg(zb + (size_t)tt * GG + row));
    float zn = __half2float(__ldg(zb + (size_t)(tt + tstep) * GG + row));

    for (int s = 0; s < TT; s++) {
        float zcur = zc;
        zc = zn;
        if (s + 2 < TT)
            zn = __half2float(__ldg(zb + (size_t)(tt + 2 * tstep) * GG + row));

        const uint4* hr = reinterpret_cast<const uint4*>(&hs[s & 1][0]);
        const __half2 zz = __float2half2_rn(0.f);
        __half2 p0 = zz, p1 = zz, p2 = zz, p3 = zz;
        #pragma unroll
        for (int k = 0; k < 16; k++) {
            uint4 v = hr[k];
            p0 = __hfma2(wv[4*k+0], u2h(v.x), p0);
            p1 = __hfma2(wv[4*k+1], u2h(v.y), p1);
            p2 = __hfma2(wv[4*k+2], u2h(v.z), p2);
            p3 = __hfma2(wv[4*k+3], u2h(v.w), p3);
        }
        float sv = zcur + hsum4(p0, p1, p2, p3);

        // per-quarter activation (parallel across all 512 threads)
        float n = (q == 2) ? tanha(sv) : sigm(sv);

        // hop 1: q2->q0 (g-act), q3->q1 (o-act)
        float r16 = __shfl_down_sync(0xffffffffu, n, 16);
        // pack: q0 holds (i, g), q1 holds (f, o)
        uint32_t pk = h2u(__floats2half2_rn(n, r16));
        // hop 2: q1 -> q0
        uint32_t r8 = __shfl_down_sync(0xffffffffu, pk, 8);

        if (q == 0) {
            __half2 ig = u2h(pk);   // (sigm i, tanh g)
            __half2 fo = u2h(r8);   // (sigm f, sigm o)
            float iv = __low2float(ig), gv = __high2float(ig);
            float fv = __low2float(fo), ov = __high2float(fo);
            cst = fv * cst + iv * gv;
            float hv = ov * ftanh(cst);
            __half hh = __float2half(hv);
            hs[(s + 1) & 1][e] = hh;
            ydst[(size_t)tt * H2] = hh;
        }
        __syncthreads();
        tt += tstep;
    }
}

// ---------------- K3: attention logits via mma.sync ----------------
#define K3_WA   0
#define K3_YS   135168
#define K3_BW   202752
#define K3_TOT  204800

__global__ void __launch_bounds__(256) k3_mma(
    const float* __restrict__ ba, const float* __restrict__ Wu)
{
    extern __shared__ __align__(16) char smem[];
    const int tid = threadIdx.x;
    const int t0 = blockIdx.x * 128;
    const int b  = blockIdx.y;

    {
        const uint4* src = reinterpret_cast<const uint4*>(g_Wa_h);
        #pragma unroll
        for (int i = 0; i < 32; i++) {
            int idx = i * 256 + tid;
            int r = idx >> 5, c = idx & 31;
            *reinterpret_cast<uint4*>(smem + K3_WA + r * 528 + c * 16) = __ldg(src + idx);
        }
    }
    {
        const uint4* src = reinterpret_cast<const uint4*>(&g_y[b][t0][0]);
        #pragma unroll
        for (int i = 0; i < 16; i++) {
            int idx = i * 256 + tid;
            int r = idx >> 5, c = idx & 31;
            *reinterpret_cast<uint4*>(smem + K3_YS + r * 528 + c * 16) = src[idx];
        }
    }
    *reinterpret_cast<float2*>(smem + K3_BW + tid * 8) =
        make_float2(__ldg(ba + tid), __ldg(Wu + tid));
    __syncthreads();

    const int w = tid >> 5, lane = tid & 31;
    const int qr = lane >> 2, q4 = lane & 3;
    const int m0 = w * 16;

    uint32_t afr[16][4];
    {
        const char* yb = smem + K3_YS;
        #pragma unroll
        for (int kt = 0; kt < 16; kt++) {
            int kb = q4 * 2 + kt * 16;
            afr[kt][0] = *reinterpret_cast<const uint32_t*>(yb + (m0 + qr) * 528 + kb * 2);
            afr[kt][1] = *reinterpret_cast<const uint32_t*>(yb + (m0 + qr + 8) * 528 + kb * 2);
            afr[kt][2] = *reinterpret_cast<const uint32_t*>(yb + (m0 + qr) * 528 + (kb + 8) * 2);
            afr[kt][3] = *reinterpret_cast<const uint32_t*>(yb + (m0 + qr + 8) * 528 + (kb + 8) * 2);
        }
    }

    const char* wab = smem + K3_WA;
    const float2* bw = reinterpret_cast<const float2*>(smem + K3_BW);
    float s0 = 0.f, s1 = 0.f;

    #pragma unroll 2
    for (int j = 0; j < 32; j++) {
        float acc[4] = {0.f, 0.f, 0.f, 0.f};
        int nr = j * 8 + qr;
        #pragma unroll
        for (int kt = 0; kt < 16; kt++) {
            int kb = q4 * 2 + kt * 16;
            uint32_t b0 = *reinterpret_cast<const uint32_t*>(wab + nr * 528 + kb * 2);
            uint32_t b1 = *reinterpret_cast<const uint32_t*>(wab + nr * 528 + (kb + 8) * 2);
            mma16816(acc, afr[kt], b0, b1, acc);
        }
        int n0 = j * 8 + q4 * 2;
        float2 pp0 = bw[n0], pp1 = bw[n0 + 1];
        s0 += ftanh(acc[0] + pp0.x) * pp0.y + ftanh(acc[1] + pp1.x) * pp1.y;
        s1 += ftanh(acc[2] + pp0.x) * pp0.y + ftanh(acc[3] + pp1.x) * pp1.y;
    }
    s0 += __shfl_xor_sync(0xffffffffu, s0, 1);
    s0 += __shfl_xor_sync(0xffffffffu, s0, 2);
    s1 += __shfl_xor_sync(0xffffffffu, s1, 1);
    s1 += __shfl_xor_sync(0xffffffffu, s1, 2);
    if (q4 == 0) {
        g_scores[b][t0 + m0 + qr]     = s0;
        g_scores[b][t0 + m0 + qr + 8] = s1;
    }
}

// ---------------- K4: softmax over T + weighted sum ----------------
__global__ void __launch_bounds__(256) k4_soft(float* __restrict__ out)
{
    __shared__ float wb[TT];
    __shared__ float red[256];
    const int b = blockIdx.x, tid = threadIdx.x;

    float m = -1e30f;
    #pragma unroll
    for (int r = 0; r < 8; r++) m = fmaxf(m, g_scores[b][r * 256 + tid]);
    red[tid] = m; __syncthreads();
    for (int off = 128; off > 0; off >>= 1) {
        if (tid < off) red[tid] = fmaxf(red[tid], red[tid + off]);
        __syncthreads();
    }
    const float mx = red[0];
    __syncthreads();

    float ls = 0.f;
    #pragma unroll
    for (int r = 0; r < 8; r++) {
        int t = r * 256 + tid;
        float e = fast_ex2((g_scores[b][t] - mx) * LOG2E);
        wb[t] = e; ls += e;
    }
    red[tid] = ls; __syncthreads();
    for (int off = 128; off > 0; off >>= 1) {
        if (tid < off) red[tid] += red[tid + off];
        __syncthreads();
    }
    const float rz = __frcp_rn(red[0]);

    float acc = 0.f;
    const __half* yp = &g_y[b][0][tid];
    for (int t = 0; t < TT; t += 8) {
        #pragma unroll
        for (int u = 0; u < 8; u++)
            acc += wb[t + u] * __half2float(__ldg(yp + (size_t)(t + u) * H2));
    }
    out[b * H2 + tid] = acc * rz;
}

// ---------------- launch ----------------
extern "C" void kernel_launch(void* const* d_in, const int* in_sizes, int n_in,
                              void* d_out, int out_size)
{
    const float* x     = (const float*)d_in[0];
    const float* Wih_f = (const float*)d_in[1];
    const float* Whh_f = (const float*)d_in[2];
    const float* bih_f = (const float*)d_in[3];
    const float* bhh_f = (const float*)d_in[4];
    const float* Wih_b = (const float*)d_in[5];
    const float* Whh_b = (const float*)d_in[6];
    const float* bih_b = (const float*)d_in[7];
    const float* bhh_b = (const float*)d_in[8];
    const float* Wa    = (const float*)d_in[9];
    const float* ba    = (const float*)d_in[10];
    const float* Wu    = (const float*)d_in[11];
    float* out = (float*)d_out;

    cudaFuncSetAttribute(k1_mma, cudaFuncAttributeMaxDynamicSharedMemorySize, K1_TOT);
    cudaFuncSetAttribute(k3_mma, cudaFuncAttributeMaxDynamicSharedMemorySize, K3_TOT);

    p_wa<<<256, 256>>>(Wa);
    p_w1<<<256, 256>>>(Wih_f, Wih_b, bih_f, bhh_f, bih_b, bhh_b);
    k1_mma<<<dim3(TT / 128, BB), 256, K1_TOT>>>(x);
    k2_lstm<<<dim3(BB, 2), 512>>>(Whh_f, Whh_b);
    k3_mma<<<dim3(TT / 128, BB), 256, K3_TOT>>>(ba, Wu);
    k4_soft<<<BB, 256>>>(out);
}

// round 9
// speedup vs baseline: 1.9570x; 1.5262x over previous
#include <cuda_runtime.h>
#include <cuda_fp16.h>
#include <cstdint>

#define BB 64
#define CC 64
#define TT 2048
#define HH 128
#define GG 512   // 4H
#define H2 256   // 2H

// Scratch (device globals — no runtime allocation allowed)
__device__ __half g_zin[2][BB][TT][GG];     // 256 MiB input projections (bias folded)
__device__ __half g_y[BB][TT][H2];          // 64 MiB [h_fwd | h_bwd]
__device__ float  g_scores[BB][TT];         // attention logits
__device__ __align__(16) __half g_Wa_h[H2 * H2];    // Wa fp16, row-major [g][k]
__device__ __align__(16) __half g_W1h[1024 * CC];   // [Wih_f; Wih_b] fp16 row-major
__device__ float  g_b1[1024];               // bih+bhh per dir, concatenated

// ---------------- helpers ----------------
__device__ __forceinline__ float fast_ex2(float x) {
    float y; asm("ex2.approx.f32 %0, %1;" : "=f"(y) : "f"(x)); return y;
}
__device__ __forceinline__ float fast_rcp(float x) {
    float y; asm("rcp.approx.f32 %0, %1;" : "=f"(y) : "f"(x)); return y;
}
#define LOG2E 1.4426950408889634f
__device__ __forceinline__ float sigm(float x) {      // accurate (ex2+rcp)
    return fast_rcp(1.f + fast_ex2(-LOG2E * x));
}
__device__ __forceinline__ float tanha(float x) {     // accurate, for gate g
    return 1.f - 2.f * fast_rcp(1.f + fast_ex2(2.f * LOG2E * x));
}
__device__ __forceinline__ float ftanh(float x) {     // MUFU.TANH (rel_err-neutral)
    float y; asm("tanh.approx.f32 %0, %1;" : "=f"(y) : "f"(x)); return y;
}
__device__ __forceinline__ float hsum4(__half2 a, __half2 b, __half2 c, __half2 d) {
    __half2 s = __hadd2(__hadd2(a, b), __hadd2(c, d));
    return __low2float(s) + __high2float(s);
}
__device__ __forceinline__ __half2 u2h(unsigned u) {
    return *reinterpret_cast<__half2*>(&u);
}
__device__ __forceinline__ uint32_t h2u(__half2 h) {
    return *reinterpret_cast<uint32_t*>(&h);
}

// m16n8k16 row.col f16 -> f32 (base-target PTX, lowers to HMMA on sm_103)
__device__ __forceinline__ void mma16816(float* d, const uint32_t* a,
                                         uint32_t b0, uint32_t b1, const float* c) {
    asm volatile(
        "mma.sync.aligned.m16n8k16.row.col.f32.f16.f16.f32 "
        "{%0,%1,%2,%3}, {%4,%5,%6,%7}, {%8,%9}, {%10,%11,%12,%13};"
        : "=f"(d[0]), "=f"(d[1]), "=f"(d[2]), "=f"(d[3])
        : "r"(a[0]), "r"(a[1]), "r"(a[2]), "r"(a[3]),
          "r"(b0), "r"(b1),
          "f"(c[0]), "f"(c[1]), "f"(c[2]), "f"(c[3]));
}

// ---------------- prep kernels (tiny) ----------------
__global__ void __launch_bounds__(256) p_wa(const float* __restrict__ Wa) {
    int i = blockIdx.x * 256 + threadIdx.x;
    g_Wa_h[i] = __float2half(__ldg(Wa + i));
}
__global__ void __launch_bounds__(256) p_w1(
    const float* __restrict__ Wf, const float* __restrict__ Wb,
    const float* __restrict__ bif, const float* __restrict__ bhf,
    const float* __restrict__ bib, const float* __restrict__ bhb)
{
    int i = blockIdx.x * 256 + threadIdx.x;
    g_W1h[i] = __float2half(i < 32768 ? __ldg(Wf + i) : __ldg(Wb + i - 32768));
    if (i < 512)       g_b1[i] = __ldg(bif + i) + __ldg(bhf + i);
    else if (i < 1024) g_b1[i] = __ldg(bib + i - 512) + __ldg(bhb + i - 512);
}

// ---------------- K1: z = x_tile @ W1^T + bias via mma.sync ----------------
#define K1_WS   0
#define K1_XS   147456
#define K1_BS   164352
#define K1_TOT  168448

__global__ void __launch_bounds__(256) k1_mma(const float* __restrict__ x)
{
    extern __shared__ __align__(16) char smem[];
    const int tid = threadIdx.x;
    const int t0 = blockIdx.x * 128;
    const int b  = blockIdx.y;

    {
        const uint4* src = reinterpret_cast<const uint4*>(g_W1h);
        #pragma unroll
        for (int i = 0; i < 32; i++) {
            int idx = i * 256 + tid;
            int r = idx >> 3, c = idx & 7;
            *reinterpret_cast<uint4*>(smem + K1_WS + r * 144 + c * 16) = __ldg(src + idx);
        }
    }
    #pragma unroll
    for (int i = 0; i < 32; i++) {
        int idx = i * 256 + tid;
        int c = idx >> 7, tl = idx & 127;
        float v = __ldg(x + ((size_t)b * CC + c) * TT + t0 + tl);
        *reinterpret_cast<__half*>(smem + K1_XS + tl * 132 + c * 2) = __float2half(v);
    }
    #pragma unroll
    for (int i = 0; i < 4; i++) {
        int g = i * 256 + tid;
        *reinterpret_cast<float*>(smem + K1_BS + g * 4) = g_b1[g];
    }
    __syncthreads();

    const int w = tid >> 5, lane = tid & 31;
    const int qr = lane >> 2, q4 = lane & 3;
    const int m0 = w * 16;

    uint32_t afr[4][4];
    {
        const char* xb = smem + K1_XS;
        #pragma unroll
        for (int kt = 0; kt < 4; kt++) {
            int kb = q4 * 2 + kt * 16;
            afr[kt][0] = *reinterpret_cast<const uint32_t*>(xb + (m0 + qr) * 132 + kb * 2);
            afr[kt][1] = *reinterpret_cast<const uint32_t*>(xb + (m0 + qr + 8) * 132 + kb * 2);
            afr[kt][2] = *reinterpret_cast<const uint32_t*>(xb + (m0 + qr) * 132 + (kb + 8) * 2);
            afr[kt][3] = *reinterpret_cast<const uint32_t*>(xb + (m0 + qr + 8) * 132 + (kb + 8) * 2);
        }
    }

    const char* wsb = smem + K1_WS;
    const int t_ = t0 + m0 + qr;
    #pragma unroll 4
    for (int j = 0; j < 128; j++) {
        float acc[4] = {0.f, 0.f, 0.f, 0.f};
        int nr = j * 8 + qr;
        #pragma unroll
        for (int kt = 0; kt < 4; kt++) {
            int kb = q4 * 2 + kt * 16;
            uint32_t b0 = *reinterpret_cast<const uint32_t*>(wsb + nr * 144 + kb * 2);
            uint32_t b1 = *reinterpret_cast<const uint32_t*>(wsb + nr * 144 + (kb + 8) * 2);
            mma16816(acc, afr[kt], b0, b1, acc);
        }
        int gcol = j * 8 + q4 * 2;
        float2 bs = *reinterpret_cast<const float2*>(smem + K1_BS + gcol * 4);
        int dir = gcol >> 9, g = gcol & 511;
        __half2 v01 = __floats2half2_rn(acc[0] + bs.x, acc[1] + bs.y);
        __half2 v23 = __floats2half2_rn(acc[2] + bs.x, acc[3] + bs.y);
        *reinterpret_cast<__half2*>(&g_zin[dir][b][t_][g]) = v01;
        *reinterpret_cast<__half2*>(&g_zin[dir][b][t_ + 8][g]) = v23;
    }
}

// ---------------- K2: recurrence — R4 layout + pipelined h loads ----------------
// 256 thr; warp w lane L: element e = w*16 + (L&15); hi = L>>4 (0:(i,f)+state,
// 1:(g,o)). h loads double-buffered in 4-uint4 blocks under the FMA bursts.
// One packed shfl ships (tanh g, sigm o); one barrier/step; hs double-buffered.
#define STEP4(v, k)                                              \
    p0 = __hfma2(w0[4*(k)+0], u2h((v).x), p0);                   \
    q0 = __hfma2(w1[4*(k)+0], u2h((v).x), q0);                   \
    p1 = __hfma2(w0[4*(k)+1], u2h((v).y), p1);                   \
    q1 = __hfma2(w1[4*(k)+1], u2h((v).y), q1);                   \
    p2 = __hfma2(w0[4*(k)+2], u2h((v).z), p2);                   \
    q2 = __hfma2(w1[4*(k)+2], u2h((v).z), q2);                   \
    p3 = __hfma2(w0[4*(k)+3], u2h((v).w), p3);                   \
    q3 = __hfma2(w1[4*(k)+3], u2h((v).w), q3);

__global__ void __launch_bounds__(256, 1) k2_lstm(
    const float* __restrict__ Whh_f, const float* __restrict__ Whh_b)
{
    const int b = blockIdx.x, dir = blockIdx.y, tid = threadIdx.x;
    const float* Whh = dir ? Whh_b : Whh_f;

    __shared__ __align__(16) __half hs[2][HH];

    const int w = tid >> 5, L = tid & 31;
    const int e  = w * 16 + (L & 15);
    const int hi = L >> 4;                 // 0: (i,f)+state  1: (g,o)
    const int row0 = e + hi * 256;         // i-row or g-row
    const int row1 = row0 + 128;           // f-row or o-row

    __half2 w0[64], w1[64];
    {
        const float4* P0 = reinterpret_cast<const float4*>(Whh + row0 * HH);
        const float4* P1 = reinterpret_cast<const float4*>(Whh + row1 * HH);
        #pragma unroll
        for (int k = 0; k < 32; k++) {
            float4 f = __ldg(P0 + k);
            w0[2*k]   = __floats2half2_rn(f.x, f.y);
            w0[2*k+1] = __floats2half2_rn(f.z, f.w);
            float4 g = __ldg(P1 + k);
            w1[2*k]   = __floats2half2_rn(g.x, g.y);
            w1[2*k+1] = __floats2half2_rn(g.z, g.w);
        }
    }
    if (tid < HH) {
        hs[0][tid] = __float2half(0.f);
        hs[1][tid] = __float2half(0.f);
    }
    float cst = 0.f;
    __syncthreads();

    const __half* zb = &g_zin[dir][b][0][0];
    int tt = dir ? (TT - 1) : 0;
    const int tstep = dir ? -1 : 1;
    __half* ydst = &g_y[b][0][dir * HH + e];

    // depth-2 z prefetch (2 rows/thread)
    float zc0 = __half2float(__ldg(zb + (size_t)tt * GG + row0));
    float zc1 = __half2float(__ldg(zb + (size_t)tt * GG + row1));
    float zn0 = __half2float(__ldg(zb + (size_t)(tt + tstep) * GG + row0));
    float zn1 = __half2float(__ldg(zb + (size_t)(tt + tstep) * GG + row1));

    for (int s = 0; s < TT; s++) {
        float a0 = zc0, a1 = zc1;
        zc0 = zn0; zc1 = zn1;
        if (s + 2 < TT) {
            const __half* zp = zb + (size_t)(tt + 2 * tstep) * GG;
            zn0 = __half2float(__ldg(zp + row0));
            zn1 = __half2float(__ldg(zp + row1));
        }

        const uint4* hr = reinterpret_cast<const uint4*>(&hs[s & 1][0]);
        const __half2 zz = __float2half2_rn(0.f);
        __half2 p0 = zz, p1 = zz, p2 = zz, p3 = zz;
        __half2 q0 = zz, q1 = zz, q2 = zz, q3 = zz;

        // block 0 loads (exposed once), then each block's loads hide under
        // the previous block's 64-FMA burst.
        uint4 ha0 = hr[0],  ha1 = hr[1],  ha2 = hr[2],  ha3 = hr[3];
        uint4 hb0 = hr[4],  hb1 = hr[5],  hb2 = hr[6],  hb3 = hr[7];
        STEP4(ha0, 0)  STEP4(ha1, 1)  STEP4(ha2, 2)  STEP4(ha3, 3)
        ha0 = hr[8];  ha1 = hr[9];  ha2 = hr[10]; ha3 = hr[11];
        STEP4(hb0, 4)  STEP4(hb1, 5)  STEP4(hb2, 6)  STEP4(hb3, 7)
        hb0 = hr[12]; hb1 = hr[13]; hb2 = hr[14]; hb3 = hr[15];
        STEP4(ha0, 8)  STEP4(ha1, 9)  STEP4(ha2, 10) STEP4(ha3, 11)
        STEP4(hb0, 12) STEP4(hb1, 13) STEP4(hb2, 14) STEP4(hb3, 15)

        float s0 = a0 + hsum4(p0, p1, p2, p3);
        float s1 = a1 + hsum4(q0, q1, q2, q3);

        // lanes<16: (sigm i, sigm f); lanes>=16: (tanh g, sigm o)
        float n0 = hi ? tanha(s0) : sigm(s0);
        float n1 = sigm(s1);
        uint32_t pk = h2u(__floats2half2_rn(n0, n1));
        uint32_t r  = __shfl_down_sync(0xffffffffu, pk, 16);

        if (hi == 0) {
            __half2 go = u2h(r);            // (tanh g, sigm o)
            float gv = __low2float(go), ov = __high2float(go);
            cst = n1 * cst + n0 * gv;       // c = sf*c + si*tg
            float hv = ov * ftanh(cst);
            __half hh = __float2half(hv);
            hs[(s + 1) & 1][e] = hh;
            ydst[(size_t)tt * H2] = hh;
        }
        __syncthreads();
        tt += tstep;
    }
}

// ---------------- K3: attention logits via mma.sync ----------------
#define K3_WA   0
#define K3_YS   135168
#define K3_BW   202752
#define K3_TOT  204800

__global__ void __launch_bounds__(256) k3_mma(
    const float* __restrict__ ba, const float* __restrict__ Wu)
{
    extern __shared__ __align__(16) char smem[];
    const int tid = threadIdx.x;
    const int t0 = blockIdx.x * 128;
    const int b  = blockIdx.y;

    {
        const uint4* src = reinterpret_cast<const uint4*>(g_Wa_h);
        #pragma unroll
        for (int i = 0; i < 32; i++) {
            int idx = i * 256 + tid;
            int r = idx >> 5, c = idx & 31;
            *reinterpret_cast<uint4*>(smem + K3_WA + r * 528 + c * 16) = __ldg(src + idx);
        }
    }
    {
        const uint4* src = reinterpret_cast<const uint4*>(&g_y[b][t0][0]);
        #pragma unroll
        for (int i = 0; i < 16; i++) {
            int idx = i * 256 + tid;
            int r = idx >> 5, c = idx & 31;
            *reinterpret_cast<uint4*>(smem + K3_YS + r * 528 + c * 16) = src[idx];
        }
    }
    *reinterpret_cast<float2*>(smem + K3_BW + tid * 8) =
        make_float2(__ldg(ba + tid), __ldg(Wu + tid));
    __syncthreads();

    const int w = tid >> 5, lane = tid & 31;
    const int qr = lane >> 2, q4 = lane & 3;
    const int m0 = w * 16;

    uint32_t afr[16][4];
    {
        const char* yb = smem + K3_YS;
        #pragma unroll
        for (int kt = 0; kt < 16; kt++) {
            int kb = q4 * 2 + kt * 16;
            afr[kt][0] = *reinterpret_cast<const uint32_t*>(yb + (m0 + qr) * 528 + kb * 2);
            afr[kt][1] = *reinterpret_cast<const uint32_t*>(yb + (m0 + qr + 8) * 528 + kb * 2);
            afr[kt][2] = *reinterpret_cast<const uint32_t*>(yb + (m0 + qr) * 528 + (kb + 8) * 2);
            afr[kt][3] = *reinterpret_cast<const uint32_t*>(yb + (m0 + qr + 8) * 528 + (kb + 8) * 2);
        }
    }

    const char* wab = smem + K3_WA;
    const float2* bw = reinterpret_cast<const float2*>(smem + K3_BW);
    float s0 = 0.f, s1 = 0.f;

    #pragma unroll 2
    for (int j = 0; j < 32; j++) {
        float acc[4] = {0.f, 0.f, 0.f, 0.f};
        int nr = j * 8 + qr;
        #pragma unroll
        for (int kt = 0; kt < 16; kt++) {
            int kb = q4 * 2 + kt * 16;
            uint32_t b0 = *reinterpret_cast<const uint32_t*>(wab + nr * 528 + kb * 2);
            uint32_t b1 = *reinterpret_cast<const uint32_t*>(wab + nr * 528 + (kb + 8) * 2);
            mma16816(acc, afr[kt], b0, b1, acc);
        }
        int n0 = j * 8 + q4 * 2;
        float2 pp0 = bw[n0], pp1 = bw[n0 + 1];
        s0 += ftanh(acc[0] + pp0.x) * pp0.y + ftanh(acc[1] + pp1.x) * pp1.y;
        s1 += ftanh(acc[2] + pp0.x) * pp0.y + ftanh(acc[3] + pp1.x) * pp1.y;
    }
    s0 += __shfl_xor_sync(0xffffffffu, s0, 1);
    s0 += __shfl_xor_sync(0xffffffffu, s0, 2);
    s1 += __shfl_xor_sync(0xffffffffu, s1, 1);
    s1 += __shfl_xor_sync(0xffffffffu, s1, 2);
    if (q4 == 0) {
        g_scores[b][t0 + m0 + qr]     = s0;
        g_scores[b][t0 + m0 + qr + 8] = s1;
    }
}

// ---------------- K4: softmax over T + weighted sum ----------------
__global__ void __launch_bounds__(256) k4_soft(float* __restrict__ out)
{
    __shared__ float wb[TT];
    __shared__ float red[256];
    const int b = blockIdx.x, tid = threadIdx.x;

    float m = -1e30f;
    #pragma unroll
    for (int r = 0; r < 8; r++) m = fmaxf(m, g_scores[b][r * 256 + tid]);
    red[tid] = m; __syncthreads();
    for (int off = 128; off > 0; off >>= 1) {
        if (tid < off) red[tid] = fmaxf(red[tid], red[tid + off]);
        __syncthreads();
    }
    const float mx = red[0];
    __syncthreads();

    float ls = 0.f;
    #pragma unroll
    for (int r = 0; r < 8; r++) {
        int t = r * 256 + tid;
        float e = fast_ex2((g_scores[b][t] - mx) * LOG2E);
        wb[t] = e; ls += e;
    }
    red[tid] = ls; __syncthreads();
    for (int off = 128; off > 0; off >>= 1) {
        if (tid < off) red[tid] += red[tid + off];
        __syncthreads();
    }
    const float rz = __frcp_rn(red[0]);

    float acc = 0.f;
    const __half* yp = &g_y[b][0][tid];
    for (int t = 0; t < TT; t += 8) {
        #pragma unroll
        for (int u = 0; u < 8; u++)
            acc += wb[t + u] * __half2float(__ldg(yp + (size_t)(t + u) * H2));
    }
    out[b * H2 + tid] = acc * rz;
}

// ---------------- launch ----------------
extern "C" void kernel_launch(void* const* d_in, const int* in_sizes, int n_in,
                              void* d_out, int out_size)
{
    const float* x     = (const float*)d_in[0];
    const float* Wih_f = (const float*)d_in[1];
    const float* Whh_f = (const float*)d_in[2];
    const float* bih_f = (const float*)d_in[3];
    const float* bhh_f = (const float*)d_in[4];
    const float* Wih_b = (const float*)d_in[5];
    const float* Whh_b = (const float*)d_in[6];
    const float* bih_b = (const float*)d_in[7];
    const float* bhh_b = (const float*)d_in[8];
    const float* Wa    = (const float*)d_in[9];
    const float* ba    = (const float*)d_in[10];
    const float* Wu    = (const float*)d_in[11];
    float* out = (float*)d_out;

    cudaFuncSetAttribute(k1_mma, cudaFuncAttributeMaxDynamicSharedMemorySize, K1_TOT);
    cudaFuncSetAttribute(k3_mma, cudaFuncAttributeMaxDynamicSharedMemorySize, K3_TOT);

    p_wa<<<256, 256>>>(Wa);
    p_w1<<<256, 256>>>(Wih_f, Wih_b, bih_f, bhh_f, bih_b, bhh_b);
    k1_mma<<<dim3(TT / 128, BB), 256, K1_TOT>>>(x);
    k2_lstm<<<dim3(BB, 2), 256>>>(Whh_f, Whh_b);
    k3_mma<<<dim3(TT / 128, BB), 256, K3_TOT>>>(ba, Wu);
    k4_soft<<<BB, 256>>>(out);
}

// round 10
// speedup vs baseline: 2.4475x; 1.2507x over previous
#include <cuda_runtime.h>
#include <cuda_fp16.h>
#include <cstdint>

#define BB 64
#define CC 64
#define TT 2048
#define HH 128
#define GG 512   // 4H
#define H2 256   // 2H

// Scratch (device globals — no runtime allocation allowed)
__device__ __half g_zin[2][BB][TT][GG];     // 256 MiB input projections (bias folded)
__device__ __half g_y[BB][TT][H2];          // 64 MiB [h_fwd | h_bwd]
__device__ float  g_scores[BB][TT];         // attention logits
__device__ __align__(16) __half g_Wa_h[H2 * H2];    // Wa fp16, row-major [g][k]
__device__ __align__(16) __half g_W1h[1024 * CC];   // [Wih_f; Wih_b] fp16 row-major
__device__ float  g_b1[1024];               // bih+bhh per dir, concatenated

// ---------------- helpers ----------------
__device__ __forceinline__ float fast_ex2(float x) {
    float y; asm("ex2.approx.f32 %0, %1;" : "=f"(y) : "f"(x)); return y;
}
#define LOG2E 1.4426950408889634f
__device__ __forceinline__ float ftanh(float x) {     // MUFU.TANH
    float y; asm("tanh.approx.f32 %0, %1;" : "=f"(y) : "f"(x)); return y;
}
__device__ __forceinline__ float fsigm(float x) {     // sigma via MUFU.TANH
    return fmaf(ftanh(0.5f * x), 0.5f, 0.5f);
}
__device__ __forceinline__ float hsum4(__half2 a, __half2 b, __half2 c, __half2 d) {
    __half2 s = __hadd2(__hadd2(a, b), __hadd2(c, d));
    return __low2float(s) + __high2float(s);
}
__device__ __forceinline__ __half2 u2h(unsigned u) {
    return *reinterpret_cast<__half2*>(&u);
}
__device__ __forceinline__ uint32_t h2u(__half2 h) {
    return *reinterpret_cast<uint32_t*>(&h);
}

// m16n8k16 row.col f16 -> f32 (base-target PTX, lowers to HMMA on sm_103)
__device__ __forceinline__ void mma16816(float* d, const uint32_t* a,
                                         uint32_t b0, uint32_t b1, const float* c) {
    asm volatile(
        "mma.sync.aligned.m16n8k16.row.col.f32.f16.f16.f32 "
        "{%0,%1,%2,%3}, {%4,%5,%6,%7}, {%8,%9}, {%10,%11,%12,%13};"
        : "=f"(d[0]), "=f"(d[1]), "=f"(d[2]), "=f"(d[3])
        : "r"(a[0]), "r"(a[1]), "r"(a[2]), "r"(a[3]),
          "r"(b0), "r"(b1),
          "f"(c[0]), "f"(c[1]), "f"(c[2]), "f"(c[3]));
}

// ---------------- prep: Wa + W1 + biases in one kernel ----------------
__global__ void __launch_bounds__(256) p_prep(
    const float* __restrict__ Wa,
    const float* __restrict__ Wf, const float* __restrict__ Wb,
    const float* __restrict__ bif, const float* __restrict__ bhf,
    const float* __restrict__ bib, const float* __restrict__ bhb)
{
    int i = blockIdx.x * 256 + threadIdx.x;           // 0..65535
    g_Wa_h[i] = __float2half(__ldg(Wa + i));
    g_W1h[i]  = __float2half(i < 32768 ? __ldg(Wf + i) : __ldg(Wb + i - 32768));
    if (i < 512)       g_b1[i] = __ldg(bif + i) + __ldg(bhf + i);
    else if (i < 1024) g_b1[i] = __ldg(bib + i - 512) + __ldg(bhb + i - 512);
}

// ---------------- K1: z = x_tile @ W1^T + bias via mma.sync ----------------
#define K1_WS   0
#define K1_XS   147456
#define K1_BS   164352
#define K1_TOT  168448

__global__ void __launch_bounds__(256) k1_mma(const float* __restrict__ x)
{
    extern __shared__ __align__(16) char smem[];
    const int tid = threadIdx.x;
    const int t0 = blockIdx.x * 128;
    const int b  = blockIdx.y;

    {
        const uint4* src = reinterpret_cast<const uint4*>(g_W1h);
        #pragma unroll
        for (int i = 0; i < 32; i++) {
            int idx = i * 256 + tid;
            int r = idx >> 3, c = idx & 7;
            *reinterpret_cast<uint4*>(smem + K1_WS + r * 144 + c * 16) = __ldg(src + idx);
        }
    }
    #pragma unroll
    for (int i = 0; i < 32; i++) {
        int idx = i * 256 + tid;
        int c = idx >> 7, tl = idx & 127;
        float v = __ldg(x + ((size_t)b * CC + c) * TT + t0 + tl);
        *reinterpret_cast<__half*>(smem + K1_XS + tl * 132 + c * 2) = __float2half(v);
    }
    #pragma unroll
    for (int i = 0; i < 4; i++) {
        int g = i * 256 + tid;
        *reinterpret_cast<float*>(smem + K1_BS + g * 4) = g_b1[g];
    }
    __syncthreads();

    const int w = tid >> 5, lane = tid & 31;
    const int qr = lane >> 2, q4 = lane & 3;
    const int m0 = w * 16;

    uint32_t afr[4][4];
    {
        const char* xb = smem + K1_XS;
        #pragma unroll
        for (int kt = 0; kt < 4; kt++) {
            int kb = q4 * 2 + kt * 16;
            afr[kt][0] = *reinterpret_cast<const uint32_t*>(xb + (m0 + qr) * 132 + kb * 2);
            afr[kt][1] = *reinterpret_cast<const uint32_t*>(xb + (m0 + qr + 8) * 132 + kb * 2);
            afr[kt][2] = *reinterpret_cast<const uint32_t*>(xb + (m0 + qr) * 132 + (kb + 8) * 2);
            afr[kt][3] = *reinterpret_cast<const uint32_t*>(xb + (m0 + qr + 8) * 132 + (kb + 8) * 2);
        }
    }

    const char* wsb = smem + K1_WS;
    const int t_ = t0 + m0 + qr;
    #pragma unroll 4
    for (int j = 0; j < 128; j++) {
        float acc[4] = {0.f, 0.f, 0.f, 0.f};
        int nr = j * 8 + qr;
        #pragma unroll
        for (int kt = 0; kt < 4; kt++) {
            int kb = q4 * 2 + kt * 16;
            uint32_t b0 = *reinterpret_cast<const uint32_t*>(wsb + nr * 144 + kb * 2);
            uint32_t b1 = *reinterpret_cast<const uint32_t*>(wsb + nr * 144 + (kb + 8) * 2);
            mma16816(acc, afr[kt], b0, b1, acc);
        }
        int gcol = j * 8 + q4 * 2;
        float2 bs = *reinterpret_cast<const float2*>(smem + K1_BS + gcol * 4);
        int dir = gcol >> 9, g = gcol & 511;
        __half2 v01 = __floats2half2_rn(acc[0] + bs.x, acc[1] + bs.y);
        __half2 v23 = __floats2half2_rn(acc[2] + bs.x, acc[3] + bs.y);
        *reinterpret_cast<__half2*>(&g_zin[dir][b][t_][g]) = v01;
        *reinterpret_cast<__half2*>(&g_zin[dir][b][t_ + 8][g]) = v23;
    }
}

// ---------------- K2: recurrence — R9 layout, MUFU-shortened tail ----------------
#define STEP4(v, k)                                              \
    p0 = __hfma2(w0[4*(k)+0], u2h((v).x), p0);                   \
    q0 = __hfma2(w1[4*(k)+0], u2h((v).x), q0);                   \
    p1 = __hfma2(w0[4*(k)+1], u2h((v).y), p1);                   \
    q1 = __hfma2(w1[4*(k)+1], u2h((v).y), q1);                   \
    p2 = __hfma2(w0[4*(k)+2], u2h((v).z), p2);                   \
    q2 = __hfma2(w1[4*(k)+2], u2h((v).z), q2);                   \
    p3 = __hfma2(w0[4*(k)+3], u2h((v).w), p3);                   \
    q3 = __hfma2(w1[4*(k)+3], u2h((v).w), q3);

__global__ void __launch_bounds__(256, 1) k2_lstm(
    const float* __restrict__ Whh_f, const float* __restrict__ Whh_b)
{
    const int b = blockIdx.x, dir = blockIdx.y, tid = threadIdx.x;
    const float* Whh = dir ? Whh_b : Whh_f;

    __shared__ __align__(16) __half hs[2][HH];

    const int w = tid >> 5, L = tid & 31;
    const int e  = w * 16 + (L & 15);
    const int hi = L >> 4;                 // 0: (i,f)+state  1: (g,o)
    const int row0 = e + hi * 256;         // i-row or g-row
    const int row1 = row0 + 128;           // f-row or o-row

    __half2 w0[64], w1[64];
    {
        const float4* P0 = reinterpret_cast<const float4*>(Whh + row0 * HH);
        const float4* P1 = reinterpret_cast<const float4*>(Whh + row1 * HH);
        #pragma unroll
        for (int k = 0; k < 32; k++) {
            float4 f = __ldg(P0 + k);
            w0[2*k]   = __floats2half2_rn(f.x, f.y);
            w0[2*k+1] = __floats2half2_rn(f.z, f.w);
            float4 g = __ldg(P1 + k);
            w1[2*k]   = __floats2half2_rn(g.x, g.y);
            w1[2*k+1] = __floats2half2_rn(g.z, g.w);
        }
    }
    if (tid < HH) {
        hs[0][tid] = __float2half(0.f);
        hs[1][tid] = __float2half(0.f);
    }
    float cst = 0.f;
    __syncthreads();

    const __half* zb = &g_zin[dir][b][0][0];
    int tt = dir ? (TT - 1) : 0;
    const int tstep = dir ? -1 : 1;
    __half* ydst = &g_y[b][0][dir * HH + e];

    // depth-2 z prefetch (2 rows/thread)
    float zc0 = __half2float(__ldg(zb + (size_t)tt * GG + row0));
    float zc1 = __half2float(__ldg(zb + (size_t)tt * GG + row1));
    float zn0 = __half2float(__ldg(zb + (size_t)(tt + tstep) * GG + row0));
    float zn1 = __half2float(__ldg(zb + (size_t)(tt + tstep) * GG + row1));

    for (int s = 0; s < TT; s++) {
        float a0 = zc0, a1 = zc1;
        zc0 = zn0; zc1 = zn1;
        if (s + 2 < TT) {
            const __half* zp = zb + (size_t)(tt + 2 * tstep) * GG;
            zn0 = __half2float(__ldg(zp + row0));
            zn1 = __half2float(__ldg(zp + row1));
        }

        const uint4* hr = reinterpret_cast<const uint4*>(&hs[s & 1][0]);
        const __half2 zz = __float2half2_rn(0.f);
        __half2 p0 = zz, p1 = zz, p2 = zz, p3 = zz;
        __half2 q0 = zz, q1 = zz, q2 = zz, q3 = zz;

        // pipelined h loads: each block's 4 LDS issue under previous FMA burst
        uint4 ha0 = hr[0],  ha1 = hr[1],  ha2 = hr[2],  ha3 = hr[3];
        uint4 hb0 = hr[4],  hb1 = hr[5],  hb2 = hr[6],  hb3 = hr[7];
        STEP4(ha0, 0)  STEP4(ha1, 1)  STEP4(ha2, 2)  STEP4(ha3, 3)
        ha0 = hr[8];  ha1 = hr[9];  ha2 = hr[10]; ha3 = hr[11];
        STEP4(hb0, 4)  STEP4(hb1, 5)  STEP4(hb2, 6)  STEP4(hb3, 7)
        hb0 = hr[12]; hb1 = hr[13]; hb2 = hr[14]; hb3 = hr[15];
        STEP4(ha0, 8)  STEP4(ha1, 9)  STEP4(ha2, 10) STEP4(ha3, 11)
        STEP4(hb0, 12) STEP4(hb1, 13) STEP4(hb2, 14) STEP4(hb3, 15)

        float s0 = a0 + hsum4(p0, p1, p2, p3);
        float s1 = a1 + hsum4(q0, q1, q2, q3);

        // lanes<16: (sigm i, sigm f); lanes>=16: (tanh g, sigm o) — all via MUFU.TANH
        float n0 = hi ? ftanh(s0) : fsigm(s0);
        float n1 = fsigm(s1);
        uint32_t pk = h2u(__floats2half2_rn(n0, n1));
        uint32_t r  = __shfl_down_sync(0xffffffffu, pk, 16);

        if (hi == 0) {
            __half2 go = u2h(r);            // (tanh g, sigm o)
            float gv = __low2float(go), ov = __high2float(go);
            cst = n1 * cst + n0 * gv;       // c = sf*c + si*tg
            float hv = ov * ftanh(cst);
            __half hh = __float2half(hv);
            hs[(s + 1) & 1][e] = hh;
            ydst[(size_t)tt * H2] = hh;
        }
        __syncthreads();
        tt += tstep;
    }
}

// ---------------- K3: attention logits via mma.sync ----------------
#define K3_WA   0
#define K3_YS   135168
#define K3_BW   202752
#define K3_TOT  204800

__global__ void __launch_bounds__(256) k3_mma(
    const float* __restrict__ ba, const float* __restrict__ Wu)
{
    extern __shared__ __align__(16) char smem[];
    const int tid = threadIdx.x;
    const int t0 = blockIdx.x * 128;
    const int b  = blockIdx.y;

    {
        const uint4* src = reinterpret_cast<const uint4*>(g_Wa_h);
        #pragma unroll
        for (int i = 0; i < 32; i++) {
            int idx = i * 256 + tid;
            int r = idx >> 5, c = idx & 31;
            *reinterpret_cast<uint4*>(smem + K3_WA + r * 528 + c * 16) = __ldg(src + idx);
        }
    }
    {
        const uint4* src = reinterpret_cast<const uint4*>(&g_y[b][t0][0]);
        #pragma unroll
        for (int i = 0; i < 16; i++) {
            int idx = i * 256 + tid;
            int r = idx >> 5, c = idx & 31;
            *reinterpret_cast<uint4*>(smem + K3_YS + r * 528 + c * 16) = src[idx];
        }
    }
    *reinterpret_cast<float2*>(smem + K3_BW + tid * 8) =
        make_float2(__ldg(ba + tid), __ldg(Wu + tid));
    __syncthreads();

    const int w = tid >> 5, lane = tid & 31;
    const int qr = lane >> 2, q4 = lane & 3;
    const int m0 = w * 16;

    uint32_t afr[16][4];
    {
        const char* yb = smem + K3_YS;
        #pragma unroll
        for (int kt = 0; kt < 16; kt++) {
            int kb = q4 * 2 + kt * 16;
            afr[kt][0] = *reinterpret_cast<const uint32_t*>(yb + (m0 + qr) * 528 + kb * 2);
            afr[kt][1] = *reinterpret_cast<const uint32_t*>(yb + (m0 + qr + 8) * 528 + kb * 2);
            afr[kt][2] = *reinterpret_cast<const uint32_t*>(yb + (m0 + qr) * 528 + (kb + 8) * 2);
            afr[kt][3] = *reinterpret_cast<const uint32_t*>(yb + (m0 + qr + 8) * 528 + (kb + 8) * 2);
        }
    }

    const char* wab = smem + K3_WA;
    const float2* bw = reinterpret_cast<const float2*>(smem + K3_BW);
    float s0 = 0.f, s1 = 0.f;

    #pragma unroll 2
    for (int j = 0; j < 32; j++) {
        float acc[4] = {0.f, 0.f, 0.f, 0.f};
        int nr = j * 8 + qr;
        #pragma unroll
        for (int kt = 0; kt < 16; kt++) {
            int kb = q4 * 2 + kt * 16;
            uint32_t b0 = *reinterpret_cast<const uint32_t*>(wab + nr * 528 + kb * 2);
            uint32_t b1 = *reinterpret_cast<const uint32_t*>(wab + nr * 528 + (kb + 8) * 2);
            mma16816(acc, afr[kt], b0, b1, acc);
        }
        int n0 = j * 8 + q4 * 2;
        float2 pp0 = bw[n0], pp1 = bw[n0 + 1];
        s0 += ftanh(acc[0] + pp0.x) * pp0.y + ftanh(acc[1] + pp1.x) * pp1.y;
        s1 += ftanh(acc[2] + pp0.x) * pp0.y + ftanh(acc[3] + pp1.x) * pp1.y;
    }
    s0 += __shfl_xor_sync(0xffffffffu, s0, 1);
    s0 += __shfl_xor_sync(0xffffffffu, s0, 2);
    s1 += __shfl_xor_sync(0xffffffffu, s1, 1);
    s1 += __shfl_xor_sync(0xffffffffu, s1, 2);
    if (q4 == 0) {
        g_scores[b][t0 + m0 + qr]     = s0;
        g_scores[b][t0 + m0 + qr + 8] = s1;
    }
}

// ---------------- K4: softmax over T + weighted sum ----------------
__global__ void __launch_bounds__(256) k4_soft(float* __restrict__ out)
{
    __shared__ float wb[TT];
    __shared__ float red[256];
    const int b = blockIdx.x, tid = threadIdx.x;

    float m = -1e30f;
    #pragma unroll
    for (int r = 0; r < 8; r++) m = fmaxf(m, g_scores[b][r * 256 + tid]);
    red[tid] = m; __syncthreads();
    for (int off = 128; off > 0; off >>= 1) {
        if (tid < off) red[tid] = fmaxf(red[tid], red[tid + off]);
        __syncthreads();
    }
    const float mx = red[0];
    __syncthreads();

    float ls = 0.f;
    #pragma unroll
    for (int r = 0; r < 8; r++) {
        int t = r * 256 + tid;
        float e = fast_ex2((g_scores[b][t] - mx) * LOG2E);
        wb[t] = e; ls += e;
    }
    red[tid] = ls; __syncthreads();
    for (int off = 128; off > 0; off >>= 1) {
        if (tid < off) red[tid] += red[tid + off];
        __syncthreads();
    }
    const float rz = __frcp_rn(red[0]);

    float acc = 0.f;
    const __half* yp = &g_y[b][0][tid];
    for (int t = 0; t < TT; t += 8) {
        #pragma unroll
        for (int u = 0; u < 8; u++)
            acc += wb[t + u] * __half2float(__ldg(yp + (size_t)(t + u) * H2));
    }
    out[b * H2 + tid] = acc * rz;
}

// ---------------- launch ----------------
extern "C" void kernel_launch(void* const* d_in, const int* in_sizes, int n_in,
                              void* d_out, int out_size)
{
    const float* x     = (const float*)d_in[0];
    const float* Wih_f = (const float*)d_in[1];
    const float* Whh_f = (const float*)d_in[2];
    const float* bih_f = (const float*)d_in[3];
    const float* bhh_f = (const float*)d_in[4];
    const float* Wih_b = (const float*)d_in[5];
    const float* Whh_b = (const float*)d_in[6];
    const float* bih_b = (const float*)d_in[7];
    const float* bhh_b = (const float*)d_in[8];
    const float* Wa    = (const float*)d_in[9];
    const float* ba    = (const float*)d_in[10];
    const float* Wu    = (const float*)d_in[11];
    float* out = (float*)d_out;

    cudaFuncSetAttribute(k1_mma, cudaFuncAttributeMaxDynamicSharedMemorySize, K1_TOT);
    cudaFuncSetAttribute(k3_mma, cudaFuncAttributeMaxDynamicSharedMemorySize, K3_TOT);

    p_prep<<<256, 256>>>(Wa, Wih_f, Wih_b, bih_f, bhh_f, bih_b, bhh_b);
    k1_mma<<<dim3(TT / 128, BB), 256, K1_TOT>>>(x);
    k2_lstm<<<dim3(BB, 2), 256>>>(Whh_f, Whh_b);
    k3_mma<<<dim3(TT / 128, BB), 256, K3_TOT>>>(ba, Wu);
    k4_soft<<<BB, 256>>>(out);
}